// round 2
// baseline (speedup 1.0000x reference)
#include <cuda_runtime.h>
#include <cstdint>

// Fixed problem shapes
#define N_IMG 48
#define Hc 128
#define Wc 128

// Scratch (allocation-free rule: __device__ globals)
__device__ float g_y1[48u * 128u * 128u * 128u];  // conv1 out [48,128,128,128]
__device__ float g_y2[48u * 32u * 128u * 128u];   // conv2 out [48,32,128,128]

// ---- packed f32x2 helpers (sm_103a FFMA2) ----------------------------------
__device__ __forceinline__ unsigned long long pk2(float lo, float hi) {
    unsigned long long r;
    asm("mov.b64 %0, {%1, %2};" : "=l"(r) : "f"(lo), "f"(hi));
    return r;
}
__device__ __forceinline__ void ffma2(unsigned long long& d,
                                      unsigned long long a,
                                      unsigned long long b) {
    asm("fma.rn.f32x2 %0, %1, %2, %0;" : "+l"(d) : "l"(a), "l"(b));
}
__device__ __forceinline__ void unpk2(float& lo, float& hi, unsigned long long v) {
    asm("mov.b64 {%0, %1}, %2;" : "=f"(lo), "=f"(hi) : "l"(v));
}

// ---------------------------------------------------------------------------
// Direct 3x3 conv, stride 1, pad 1, NCHW, built around fma.rn.f32x2.
// Block: 256 threads, 64x32 pixel tile, 8 output channels, IC chunked by 2.
// Each thread: 8 pixels = rows {ty, ty+16} x cols {tx, tx+16, tx+32, tx+48},
// packed as 4 (c, c+16) pairs x 8 oc = 32 f32x2 accumulators.
// smem row stride 80 floats (80 mod 32 == 16) -> the two half-warps (rows R,
// R+1) hit disjoint bank halves: conflict-free LDS.
// Per (ic,ky): 24 x-LDS + 24 w-LDS(broadcast) + 96 FFMA2 = 192 MACs/thread.
// FMA-pipe / issue / crossbar all balanced at the FFMA2 peak.
// ---------------------------------------------------------------------------
template<int IC, int OC, bool RELU>
__device__ __forceinline__ void conv3x3_tile2(
    const float* __restrict__ x, const float* __restrict__ w,
    const float* __restrict__ bias, float* __restrict__ y)
{
    __shared__ float sx[2][34][80];   // [ic][row][col], cols 0..65 used
    __shared__ float sw[8][2][9];

    const int tid = threadIdx.x;
    const int tx = tid & 15, ty = tid >> 4;
    const int tileX = (blockIdx.x & 1) << 6;     // 2 tiles of 64 in x
    const int tileY = (blockIdx.x >> 1) << 5;    // 4 tiles of 32 in y
    const int ocb = blockIdx.y << 3;
    const int n = blockIdx.z;

    unsigned long long acc[8][4];
#pragma unroll
    for (int o = 0; o < 8; o++)
#pragma unroll
        for (int p = 0; p < 4; p++) acc[o][p] = 0ull;

    const float* xn = x + (size_t)n * IC * (Hc * Wc);

    for (int ic0 = 0; ic0 < IC; ic0 += 2) {
        __syncthreads();
        // stage 2-channel 34x66 input tile (zero padded at image border)
        for (int e = tid; e < 2 * 34 * 66; e += 256) {
            int ic = e / (34 * 66);
            int rem = e % (34 * 66);
            int r = rem / 66, c = rem % 66;
            int gy = tileY - 1 + r, gx = tileX - 1 + c;
            float v = 0.f;
            if ((unsigned)gy < (unsigned)Hc && (unsigned)gx < (unsigned)Wc)
                v = xn[(size_t)(ic0 + ic) * (Hc * Wc) + gy * Wc + gx];
            sx[ic][r][c] = v;
        }
        // stage weights 8 oc x 2 ic x 9
        if (tid < 144) {
            int o = tid / 18, rem = tid % 18;
            sw[o][rem / 9][rem % 9] =
                w[((size_t)(ocb + o) * IC + ic0 + rem / 9) * 9 + rem % 9];
        }
        __syncthreads();

#pragma unroll
        for (int ic = 0; ic < 2; ic++) {
#pragma unroll
            for (int ky = 0; ky < 3; ky++) {
                const float* rA = &sx[ic][ty + ky][tx];
                const float* rB = &sx[ic][ty + 16 + ky][tx];
                float xa[12], xb[12];
#pragma unroll
                for (int g = 0; g < 4; g++)
#pragma unroll
                    for (int d = 0; d < 3; d++) {
                        xa[g * 3 + d] = rA[g * 16 + d];
                        xb[g * 3 + d] = rB[g * 16 + d];
                    }
#pragma unroll
                for (int kx = 0; kx < 3; kx++) {
                    unsigned long long pa0 = pk2(xa[kx],     xa[3 + kx]);
                    unsigned long long pa1 = pk2(xa[6 + kx], xa[9 + kx]);
                    unsigned long long pb0 = pk2(xb[kx],     xb[3 + kx]);
                    unsigned long long pb1 = pk2(xb[6 + kx], xb[9 + kx]);
#pragma unroll
                    for (int o = 0; o < 8; o++) {
                        float ws = sw[o][ic][ky * 3 + kx];
                        unsigned long long wp = pk2(ws, ws);
                        ffma2(acc[o][0], wp, pa0);
                        ffma2(acc[o][1], wp, pa1);
                        ffma2(acc[o][2], wp, pb0);
                        ffma2(acc[o][3], wp, pb1);
                    }
                }
            }
        }
    }

    // epilogue: unpack, bias, relu, coalesced stores
#pragma unroll
    for (int o = 0; o < 8; o++) {
        float bv = bias[ocb + o];
        float* yp = y + ((size_t)(n * OC + ocb + o) * Hc + tileY) * Wc + tileX;
        float v[8];
        unpk2(v[0], v[1], acc[o][0]);   // (ty, tx), (ty, tx+16)
        unpk2(v[2], v[3], acc[o][1]);   // (ty, tx+32), (ty, tx+48)
        unpk2(v[4], v[5], acc[o][2]);   // (ty+16, tx), (ty+16, tx+16)
        unpk2(v[6], v[7], acc[o][3]);   // (ty+16, tx+32), (ty+16, tx+48)
#pragma unroll
        for (int i = 0; i < 8; i++) {
            v[i] += bv;
            if (RELU) v[i] = fmaxf(v[i], 0.f);
        }
        float* r0 = yp + ty * Wc + tx;
        float* r1 = yp + (ty + 16) * Wc + tx;
        r0[0]  = v[0]; r0[16] = v[1]; r0[32] = v[2]; r0[48] = v[3];
        r1[0]  = v[4]; r1[16] = v[5]; r1[32] = v[6]; r1[48] = v[7];
    }
}

__global__ __launch_bounds__(256, 2) void conv1_k(
    const float* __restrict__ x, const float* __restrict__ w,
    const float* __restrict__ b)
{
    conv3x3_tile2<64, 128, true>(x, w, b, g_y1);
}

__global__ __launch_bounds__(256, 2) void conv2_k(
    const float* __restrict__ w, const float* __restrict__ b)
{
    conv3x3_tile2<128, 32, true>(g_y1, w, b, g_y2);
}

// ---------------------------------------------------------------------------
// Fused: bilinear x2 upsample (half-pixel centers, edge clamp) + 3x3 conv
// (zero pad) 32->1. Never materializes the upsampled tensor.
// ---------------------------------------------------------------------------
__global__ __launch_bounds__(256) void upconv3_k(
    const float* __restrict__ w3, const float* __restrict__ b3,
    float* __restrict__ out)
{
    __shared__ float sv[16][10][10];
    __shared__ float su[16][18][18];
    __shared__ float sw3[288];

    const int tid = threadIdx.x;
    const int tx = tid & 15, ty = tid >> 4;
    const int tileY = (blockIdx.x >> 4) << 4;
    const int tileX = (blockIdx.x & 15) << 4;
    const int n = blockIdx.y;
    const int m0 = tileY >> 1, q0 = tileX >> 1;

    for (int e = tid; e < 288; e += 256) sw3[e] = w3[e];

    float acc = 0.f;
    for (int c0 = 0; c0 < 32; c0 += 16) {
        __syncthreads();
        for (int e = tid; e < 16 * 10 * 10; e += 256) {
            int ic = e / 100, r = (e / 10) % 10, c = e % 10;
            int gy = min(max(m0 - 1 + r, 0), Hc - 1);
            int gx = min(max(q0 - 1 + c, 0), Wc - 1);
            sv[ic][r][c] =
                g_y2[((size_t)(n * 32 + c0 + ic) * Hc + gy) * Wc + gx];
        }
        __syncthreads();
        for (int e = tid; e < 16 * 18 * 18; e += 256) {
            int ic = e / 324, r = (e / 18) % 18, c = e % 18;
            int tyg = tileY - 1 + r, txg = tileX - 1 + c;
            float uv = 0.f;
            if ((unsigned)tyg < 256u && (unsigned)txg < 256u) {
                int i0y, i0x; float fy, fx;
                if (tyg & 1) { i0y = tyg >> 1;       fy = 0.25f; }
                else         { i0y = (tyg >> 1) - 1; fy = 0.75f; }
                if (txg & 1) { i0x = txg >> 1;       fx = 0.25f; }
                else         { i0x = (txg >> 1) - 1; fx = 0.75f; }
                int ly = i0y - (m0 - 1), lx = i0x - (q0 - 1);
                float v00 = sv[ic][ly][lx],     v01 = sv[ic][ly][lx + 1];
                float v10 = sv[ic][ly + 1][lx], v11 = sv[ic][ly + 1][lx + 1];
                float gy1 = 1.f - fy, gx1 = 1.f - fx;
                uv = gy1 * (gx1 * v00 + fx * v01) + fy * (gx1 * v10 + fx * v11);
            }
            su[ic][r][c] = uv;
        }
        __syncthreads();
#pragma unroll
        for (int ic = 0; ic < 16; ic++)
#pragma unroll
            for (int dy = 0; dy < 3; dy++)
#pragma unroll
                for (int dx = 0; dx < 3; dx++)
                    acc = fmaf(sw3[(c0 + ic) * 9 + dy * 3 + dx],
                               su[ic][ty + dy][tx + dx], acc);
    }
    acc += b3[0];
    out[((size_t)(n * 256) + tileY + ty) * 256 + tileX + tx] = acc;
}

// ---------------------------------------------------------------------------
extern "C" void kernel_launch(void* const* d_in, const int* in_sizes, int n_in,
                              void* d_out, int out_size)
{
    const float* x  = (const float*)d_in[0];
    // d_in[1] = to_process (identity arange), d_in[2] = batch_size: no-ops
    const float* W1 = (const float*)d_in[3];
    const float* b1 = (const float*)d_in[4];
    const float* W2 = (const float*)d_in[5];
    const float* b2 = (const float*)d_in[6];
    const float* W3 = (const float*)d_in[7];
    const float* b3 = (const float*)d_in[8];
    float* out = (float*)d_out;

    conv1_k<<<dim3(8, 16, N_IMG), 256>>>(x, W1, b1);
    conv2_k<<<dim3(8, 4, N_IMG), 256>>>(W2, b2);
    upconv3_k<<<dim3(256, N_IMG), 256>>>(W3, b3, out);
}

// round 3
// speedup vs baseline: 1.3199x; 1.3199x over previous
#include <cuda_runtime.h>
#include <cstdint>

// Fixed problem shapes
#define N_IMG 48
#define Hc 128
#define Wc 128

// Scratch (allocation-free rule: __device__ globals)
__device__ float g_y1[48u * 128u * 128u * 128u];  // conv1 out [48,128,128,128]
__device__ float g_y2[48u * 32u * 128u * 128u];   // conv2 out [48,32,128,128]

// ---------------------------------------------------------------------------
// Direct 3x3 conv, stride 1, pad 1, NCHW. Sliding-window register blocking:
// block = 256 threads covering a full-height 128x16 column stripe, 8 oc.
// Thread: 8 consecutive output rows (8*ty..8*ty+7) x 1 col (tx) x 8 oc
//         = 64 scalar accumulators.
// Per (ic,kx): 24 broadcast weight LDS + 10-row x window LDS -> 192 FFMA.
// LDS:FFMA ~ 0.18 per instr; FMA-pipe bound by construction.
// smem row stride 18: ty-groups are 144 mod 32 = 16 banks apart and 16 wide
// -> conflict-free.
// ---------------------------------------------------------------------------
#define CH 4   // ic chunk

template<int IC, int OC, bool RELU>
__device__ __forceinline__ void conv3x3_stripe(
    const float* __restrict__ x, const float* __restrict__ w,
    const float* __restrict__ bias, float* __restrict__ y)
{
    __shared__ float sx[CH][130][18];   // [ic][row+1][col+1] of the stripe
    __shared__ float sw[8][CH][9];

    const int tid = threadIdx.x;
    const int tx = tid & 15;            // col within stripe
    const int ty = tid >> 4;            // row group (8 rows each)
    const int tileX = blockIdx.x << 4;  // 8 stripes of 16 cols
    const int ocb = blockIdx.y << 3;    // 8 oc per block
    const int n = blockIdx.z;

    float acc[8][8];                    // [oc][row]
#pragma unroll
    for (int o = 0; o < 8; o++)
#pragma unroll
        for (int p = 0; p < 8; p++) acc[o][p] = 0.f;

    const float* xn = x + (size_t)n * IC * (Hc * Wc);

    for (int ic0 = 0; ic0 < IC; ic0 += CH) {
        __syncthreads();
        // stage CH-channel 130x18 stripe (rows -1..128, cols tileX-1..tileX+16)
        for (int e = tid; e < CH * 130 * 18; e += 256) {
            int ic = e / (130 * 18);
            int rem = e % (130 * 18);
            int r = rem / 18, c = rem % 18;
            int gy = r - 1, gx = tileX - 1 + c;
            float v = 0.f;
            if ((unsigned)gy < (unsigned)Hc && (unsigned)gx < (unsigned)Wc)
                v = xn[(size_t)(ic0 + ic) * (Hc * Wc) + gy * Wc + gx];
            sx[ic][r][c] = v;
        }
        // stage weights 8 oc x CH ic x 9
        for (int e = tid; e < 8 * CH * 9; e += 256) {
            int o = e / (CH * 9), rem = e % (CH * 9);
            sw[o][rem / 9][rem % 9] =
                w[((size_t)(ocb + o) * IC + ic0 + rem / 9) * 9 + rem % 9];
        }
        __syncthreads();

#pragma unroll
        for (int ic = 0; ic < CH; ic++) {
#pragma unroll
            for (int kx = 0; kx < 3; kx++) {
                // weights for this (ic,kx): 3 ky x 8 oc (broadcast LDS)
                float wv[3][8];
#pragma unroll
                for (int ky = 0; ky < 3; ky++)
#pragma unroll
                    for (int o = 0; o < 8; o++)
                        wv[ky][o] = sw[o][ic][ky * 3 + kx];
                // x window: 10 rows covering outputs 8ty..8ty+7, all ky
                float xw[10];
#pragma unroll
                for (int j = 0; j < 10; j++)
                    xw[j] = sx[ic][8 * ty + j][tx + kx];
#pragma unroll
                for (int ky = 0; ky < 3; ky++)
#pragma unroll
                    for (int p = 0; p < 8; p++) {
                        float xv = xw[p + ky];
#pragma unroll
                        for (int o = 0; o < 8; o++)
                            acc[o][p] = fmaf(wv[ky][o], xv, acc[o][p]);
                    }
            }
        }
    }

    // epilogue
#pragma unroll
    for (int o = 0; o < 8; o++) {
        float bv = bias[ocb + o];
        float* yp = y + (size_t)(n * OC + ocb + o) * (Hc * Wc) + tileX + tx;
#pragma unroll
        for (int p = 0; p < 8; p++) {
            float v = acc[o][p] + bv;
            if (RELU) v = fmaxf(v, 0.f);
            yp[(8 * ty + p) * Wc] = v;
        }
    }
}

__global__ __launch_bounds__(256, 2) void conv1_k(
    const float* __restrict__ x, const float* __restrict__ w,
    const float* __restrict__ b)
{
    conv3x3_stripe<64, 128, true>(x, w, b, g_y1);
}

__global__ __launch_bounds__(256, 2) void conv2_k(
    const float* __restrict__ w, const float* __restrict__ b)
{
    conv3x3_stripe<128, 32, true>(g_y1, w, b, g_y2);
}

// ---------------------------------------------------------------------------
// Fused: bilinear x2 upsample (half-pixel centers, edge clamp) + 3x3 conv
// (zero pad) 32->1. Never materializes the upsampled tensor.
// ---------------------------------------------------------------------------
__global__ __launch_bounds__(256) void upconv3_k(
    const float* __restrict__ w3, const float* __restrict__ b3,
    float* __restrict__ out)
{
    __shared__ float sv[16][10][10];
    __shared__ float su[16][18][18];
    __shared__ float sw3[288];

    const int tid = threadIdx.x;
    const int tx = tid & 15, ty = tid >> 4;
    const int tileY = (blockIdx.x >> 4) << 4;
    const int tileX = (blockIdx.x & 15) << 4;
    const int n = blockIdx.y;
    const int m0 = tileY >> 1, q0 = tileX >> 1;

    for (int e = tid; e < 288; e += 256) sw3[e] = w3[e];

    float acc = 0.f;
    for (int c0 = 0; c0 < 32; c0 += 16) {
        __syncthreads();
        for (int e = tid; e < 16 * 10 * 10; e += 256) {
            int ic = e / 100, r = (e / 10) % 10, c = e % 10;
            int gy = min(max(m0 - 1 + r, 0), Hc - 1);
            int gx = min(max(q0 - 1 + c, 0), Wc - 1);
            sv[ic][r][c] =
                g_y2[((size_t)(n * 32 + c0 + ic) * Hc + gy) * Wc + gx];
        }
        __syncthreads();
        for (int e = tid; e < 16 * 18 * 18; e += 256) {
            int ic = e / 324, r = (e / 18) % 18, c = e % 18;
            int tyg = tileY - 1 + r, txg = tileX - 1 + c;
            float uv = 0.f;
            if ((unsigned)tyg < 256u && (unsigned)txg < 256u) {
                int i0y, i0x; float fy, fx;
                if (tyg & 1) { i0y = tyg >> 1;       fy = 0.25f; }
                else         { i0y = (tyg >> 1) - 1; fy = 0.75f; }
                if (txg & 1) { i0x = txg >> 1;       fx = 0.25f; }
                else         { i0x = (txg >> 1) - 1; fx = 0.75f; }
                int ly = i0y - (m0 - 1), lx = i0x - (q0 - 1);
                float v00 = sv[ic][ly][lx],     v01 = sv[ic][ly][lx + 1];
                float v10 = sv[ic][ly + 1][lx], v11 = sv[ic][ly + 1][lx + 1];
                float gy1 = 1.f - fy, gx1 = 1.f - fx;
                uv = gy1 * (gx1 * v00 + fx * v01) + fy * (gx1 * v10 + fx * v11);
            }
            su[ic][r][c] = uv;
        }
        __syncthreads();
#pragma unroll
        for (int ic = 0; ic < 16; ic++)
#pragma unroll
            for (int dy = 0; dy < 3; dy++)
#pragma unroll
                for (int dx = 0; dx < 3; dx++)
                    acc = fmaf(sw3[(c0 + ic) * 9 + dy * 3 + dx],
                               su[ic][ty + dy][tx + dx], acc);
    }
    acc += b3[0];
    out[((size_t)(n * 256) + tileY + ty) * 256 + tileX + tx] = acc;
}

// ---------------------------------------------------------------------------
extern "C" void kernel_launch(void* const* d_in, const int* in_sizes, int n_in,
                              void* d_out, int out_size)
{
    const float* x  = (const float*)d_in[0];
    // d_in[1] = to_process (identity arange), d_in[2] = batch_size: no-ops
    const float* W1 = (const float*)d_in[3];
    const float* b1 = (const float*)d_in[4];
    const float* W2 = (const float*)d_in[5];
    const float* b2 = (const float*)d_in[6];
    const float* W3 = (const float*)d_in[7];
    const float* b3 = (const float*)d_in[8];
    float* out = (float*)d_out;

    conv1_k<<<dim3(8, 16, N_IMG), 256>>>(x, W1, b1);
    conv2_k<<<dim3(8, 4, N_IMG), 256>>>(W2, b2);
    upconv3_k<<<dim3(256, N_IMG), 256>>>(W3, b3, out);
}

// round 7
// speedup vs baseline: 1.4996x; 1.1361x over previous
#include <cuda_runtime.h>
#include <mma.h>
#include <cstdint>

using namespace nvcuda;

#define N_IMG 48
#define Hc 128
#define Wc 128

__device__ float g_y1[48u * 128u * 128u * 128u];   // conv1 RAW (pre-bias/relu)
__device__ float g_y2[48u * 32u * 128u * 128u];    // conv2 final

__device__ __forceinline__ float tf32r(float v) {
    uint32_t u;
    asm("cvt.rna.tf32.f32 %0, %1;" : "=r"(u) : "f"(v));
    return __uint_as_float(u);
}

// ---------------------------------------------------------------------------
// conv1 via nvcuda::wmma tf32 (m16n16k8). CTA: 256 thr, tile M=128(oc) x
// N=128 px (one image row), K=576 in chunks of 32. Warps 4(m) x 2(n); warp
// tile 32 x 64 = 2x4 fragments. Stores RAW accumulators to g_y1 with
// ldm = Hc*Wc (channel stride); conv2 applies bias+relu at read.
// ---------------------------------------------------------------------------
__global__ __launch_bounds__(256) void conv1_wmma_k(
    const float* __restrict__ w, const float* __restrict__ in)
{
    __shared__ __align__(16) float sA[128 * 40];   // [m][k_l], ldm 40
    __shared__ __align__(16) float sB[32 * 136];   // [k_l][n], ldm 136

    const int tid = threadIdx.x;
    const int wid = tid >> 5;
    const int warpM = wid >> 1, warpN = wid & 1;
    const int band = blockIdx.x;        // image row
    const int img = blockIdx.y;

    wmma::fragment<wmma::accumulator, 16, 16, 8, float> acc[2][4];
#pragma unroll
    for (int wm = 0; wm < 2; wm++)
#pragma unroll
        for (int wn = 0; wn < 4; wn++) wmma::fill_fragment(acc[wm][wn], 0.f);

    for (int c = 0; c < 18; ++c) {      // K = 576 = 18 * 32
        if (c) __syncthreads();
        // stage A: 128 m x 32 k  (k = tap*64 + ic)
        for (int e = tid; e < 128 * 32; e += 256) {
            int m = e >> 5, k_l = e & 31;
            int k = c * 32 + k_l;
            int tap = k >> 6, ic = k & 63;
            sA[m * 40 + k_l] = tf32r(w[(m * 64 + ic) * 9 + tap]);
        }
        // stage B: 32 k x 128 px im2col (zero-pad folded in)
        for (int e = tid; e < 32 * 128; e += 256) {
            int k_l = e >> 7, n = e & 127;
            int k = c * 32 + k_l;
            int tap = k >> 6, ic = k & 63;
            int yy = band + tap / 3 - 1;
            int xx = n + tap % 3 - 1;
            float v = 0.f;
            if ((unsigned)yy < (unsigned)Hc && (unsigned)xx < (unsigned)Wc)
                v = in[((size_t)(img * 64 + ic) * Hc + yy) * Wc + xx];
            sB[k_l * 136 + n] = tf32r(v);
        }
        __syncthreads();

#pragma unroll
        for (int k8 = 0; k8 < 4; ++k8) {
            wmma::fragment<wmma::matrix_a, 16, 16, 8, wmma::precision::tf32,
                           wmma::row_major> af[2];
            wmma::fragment<wmma::matrix_b, 16, 16, 8, wmma::precision::tf32,
                           wmma::row_major> bf[4];
#pragma unroll
            for (int wm = 0; wm < 2; wm++)
                wmma::load_matrix_sync(
                    af[wm], &sA[(warpM * 32 + wm * 16) * 40 + k8 * 8], 40);
#pragma unroll
            for (int wn = 0; wn < 4; wn++)
                wmma::load_matrix_sync(
                    bf[wn], &sB[(k8 * 8) * 136 + warpN * 64 + wn * 16], 136);
#pragma unroll
            for (int wm = 0; wm < 2; wm++)
#pragma unroll
                for (int wn = 0; wn < 4; wn++)
                    wmma::mma_sync(acc[wm][wn], af[wm], bf[wn], acc[wm][wn]);
        }
    }

    // store RAW: 16x16 tiles, rows = channels (stride Hc*Wc), cols = pixels
#pragma unroll
    for (int wm = 0; wm < 2; wm++)
#pragma unroll
        for (int wn = 0; wn < 4; wn++) {
            int m0 = warpM * 32 + wm * 16;
            int n0 = warpN * 64 + wn * 16;
            float* p = &g_y1[((size_t)(img * 128 + m0) * Hc + band) * Wc + n0];
            wmma::store_matrix_sync(p, acc[wm][wn], Hc * Wc,
                                    wmma::mem_row_major);
        }
}

// ---------------------------------------------------------------------------
// conv2: proven scalar stripe kernel (R3). Input fixup: g_y1 holds RAW conv1
// accumulators, so staging applies relu(raw + b1[ic]); padding stays 0.
// ---------------------------------------------------------------------------
#define CH 4

__global__ __launch_bounds__(256, 2) void conv2_k(
    const float* __restrict__ w, const float* __restrict__ bias,
    const float* __restrict__ b1)
{
    constexpr int IC = 128, OC = 32;
    __shared__ float sx[CH][130][18];
    __shared__ float sw[8][CH][9];

    const int tid = threadIdx.x;
    const int tx = tid & 15;
    const int ty = tid >> 4;
    const int tileX = blockIdx.x << 4;
    const int ocb = blockIdx.y << 3;
    const int n = blockIdx.z;

    float acc[8][8];
#pragma unroll
    for (int o = 0; o < 8; o++)
#pragma unroll
        for (int p = 0; p < 8; p++) acc[o][p] = 0.f;

    for (int ic0 = 0; ic0 < IC; ic0 += CH) {
        __syncthreads();
        for (int e = tid; e < CH * 130 * 18; e += 256) {
            int ic = e / (130 * 18);
            int rem = e % (130 * 18);
            int r = rem / 18, cc = rem % 18;
            int gy = r - 1, gx = tileX - 1 + cc;
            float v = 0.f;
            if ((unsigned)gy < (unsigned)Hc && (unsigned)gx < (unsigned)Wc)
                v = fmaxf(g_y1[(size_t)(n * IC + ic0 + ic) * (Hc * Wc) +
                               gy * Wc + gx] + b1[ic0 + ic], 0.f);
            sx[ic][r][cc] = v;
        }
        for (int e = tid; e < 8 * CH * 9; e += 256) {
            int o = e / (CH * 9), rem = e % (CH * 9);
            sw[o][rem / 9][rem % 9] =
                w[((size_t)(ocb + o) * IC + ic0 + rem / 9) * 9 + rem % 9];
        }
        __syncthreads();

#pragma unroll
        for (int ic = 0; ic < CH; ic++) {
#pragma unroll
            for (int kx = 0; kx < 3; kx++) {
                float wv[3][8];
#pragma unroll
                for (int ky = 0; ky < 3; ky++)
#pragma unroll
                    for (int o = 0; o < 8; o++)
                        wv[ky][o] = sw[o][ic][ky * 3 + kx];
                float xw[10];
#pragma unroll
                for (int j = 0; j < 10; j++)
                    xw[j] = sx[ic][8 * ty + j][tx + kx];
#pragma unroll
                for (int ky = 0; ky < 3; ky++)
#pragma unroll
                    for (int p = 0; p < 8; p++) {
                        float xv = xw[p + ky];
#pragma unroll
                        for (int o = 0; o < 8; o++)
                            acc[o][p] = fmaf(wv[ky][o], xv, acc[o][p]);
                    }
            }
        }
    }

#pragma unroll
    for (int o = 0; o < 8; o++) {
        float bv = bias[ocb + o];
        float* yp = g_y2 + (size_t)(n * OC + ocb + o) * (Hc * Wc) + tileX + tx;
#pragma unroll
        for (int p = 0; p < 8; p++) {
            float v = fmaxf(acc[o][p] + bv, 0.f);
            yp[(8 * ty + p) * Wc] = v;
        }
    }
}

// ---------------------------------------------------------------------------
// Fused bilinear x2 upsample (half-pixel, edge clamp) + 3x3 conv 32->1.
// ---------------------------------------------------------------------------
__global__ __launch_bounds__(256) void upconv3_k(
    const float* __restrict__ w3, const float* __restrict__ b3,
    float* __restrict__ out)
{
    __shared__ float sv[16][10][10];
    __shared__ float su[16][18][18];
    __shared__ float sw3[288];

    const int tid = threadIdx.x;
    const int tx = tid & 15, ty = tid >> 4;
    const int tileY = (blockIdx.x >> 4) << 4;
    const int tileX = (blockIdx.x & 15) << 4;
    const int n = blockIdx.y;
    const int m0 = tileY >> 1, q0 = tileX >> 1;

    for (int e = tid; e < 288; e += 256) sw3[e] = w3[e];

    float acc = 0.f;
    for (int c0 = 0; c0 < 32; c0 += 16) {
        __syncthreads();
        for (int e = tid; e < 16 * 10 * 10; e += 256) {
            int ic = e / 100, r = (e / 10) % 10, c = e % 10;
            int gy = min(max(m0 - 1 + r, 0), Hc - 1);
            int gx = min(max(q0 - 1 + c, 0), Wc - 1);
            sv[ic][r][c] =
                g_y2[((size_t)(n * 32 + c0 + ic) * Hc + gy) * Wc + gx];
        }
        __syncthreads();
        for (int e = tid; e < 16 * 18 * 18; e += 256) {
            int ic = e / 324, r = (e / 18) % 18, c = e % 18;
            int tyg = tileY - 1 + r, txg = tileX - 1 + c;
            float uv = 0.f;
            if ((unsigned)tyg < 256u && (unsigned)txg < 256u) {
                int i0y, i0x; float fy, fx;
                if (tyg & 1) { i0y = tyg >> 1;       fy = 0.25f; }
                else         { i0y = (tyg >> 1) - 1; fy = 0.75f; }
                if (txg & 1) { i0x = txg >> 1;       fx = 0.25f; }
                else         { i0x = (txg >> 1) - 1; fx = 0.75f; }
                int ly = i0y - (m0 - 1), lx = i0x - (q0 - 1);
                float v00 = sv[ic][ly][lx],     v01 = sv[ic][ly][lx + 1];
                float v10 = sv[ic][ly + 1][lx], v11 = sv[ic][ly + 1][lx + 1];
                float gy1 = 1.f - fy, gx1 = 1.f - fx;
                uv = gy1 * (gx1 * v00 + fx * v01) + fy * (gx1 * v10 + fx * v11);
            }
            su[ic][r][c] = uv;
        }
        __syncthreads();
#pragma unroll
        for (int ic = 0; ic < 16; ic++)
#pragma unroll
            for (int dy = 0; dy < 3; dy++)
#pragma unroll
                for (int dx = 0; dx < 3; dx++)
                    acc = fmaf(sw3[(c0 + ic) * 9 + dy * 3 + dx],
                               su[ic][ty + dy][tx + dx], acc);
    }
    acc += b3[0];
    out[((size_t)(n * 256) + tileY + ty) * 256 + tileX + tx] = acc;
}

// ---------------------------------------------------------------------------
extern "C" void kernel_launch(void* const* d_in, const int* in_sizes, int n_in,
                              void* d_out, int out_size)
{
    const float* x  = (const float*)d_in[0];
    const float* W1 = (const float*)d_in[3];
    const float* b1 = (const float*)d_in[4];
    const float* W2 = (const float*)d_in[5];
    const float* b2 = (const float*)d_in[6];
    const float* W3 = (const float*)d_in[7];
    const float* b3 = (const float*)d_in[8];
    float* out = (float*)d_out;

    conv1_wmma_k<<<dim3(Hc, N_IMG), 256>>>(W1, x);
    conv2_k<<<dim3(8, 4, N_IMG), 256>>>(W2, b2, b1);
    upconv3_k<<<dim3(256, N_IMG), 256>>>(W3, b3, out);
}

// round 9
// speedup vs baseline: 1.8397x; 1.2268x over previous
#include <cuda_runtime.h>
#include <mma.h>
#include <cstdint>

using namespace nvcuda;

#define N_IMG 48
#define Hc 128
#define Wc 128

__device__ float g_y1[48u * 128u * 128u * 128u];   // conv1 RAW (pre-bias/relu)
__device__ float g_y2[48u * 32u * 128u * 128u];    // conv2 RAW (pre-bias/relu)

__device__ __forceinline__ float tf32r(float v) {
    uint32_t u;
    asm("cvt.rna.tf32.f32 %0, %1;" : "=r"(u) : "f"(v));
    return __uint_as_float(u);
}

// ---------------------------------------------------------------------------
// conv1 via nvcuda::wmma tf32 (m16n16k8). Identical to the R7 passing kernel
// except __launch_bounds__(256,2): regs<=128 -> 2 CTAs/SM (was 142 -> 1).
// CTA: M=128(oc) x N=128 px (one image row), K=576 in chunks of 32.
// Warps 4(m) x 2(n); warp tile 32 x 64. Stores RAW accumulators.
// ---------------------------------------------------------------------------
__global__ __launch_bounds__(256, 2) void conv1_wmma_k(
    const float* __restrict__ w, const float* __restrict__ in)
{
    __shared__ __align__(16) float sA[128 * 40];   // [m][k_l], ldm 40
    __shared__ __align__(16) float sB[32 * 136];   // [k_l][n], ldm 136

    const int tid = threadIdx.x;
    const int wid = tid >> 5;
    const int warpM = wid >> 1, warpN = wid & 1;
    const int band = blockIdx.x;        // image row
    const int img = blockIdx.y;

    wmma::fragment<wmma::accumulator, 16, 16, 8, float> acc[2][4];
#pragma unroll
    for (int wm = 0; wm < 2; wm++)
#pragma unroll
        for (int wn = 0; wn < 4; wn++) wmma::fill_fragment(acc[wm][wn], 0.f);

    for (int c = 0; c < 18; ++c) {      // K = 576 = 18 * 32
        if (c) __syncthreads();
        // stage A: 128 m x 32 k  (k = tap*64 + ic)
        for (int e = tid; e < 128 * 32; e += 256) {
            int m = e >> 5, k_l = e & 31;
            int k = c * 32 + k_l;
            int tap = k >> 6, ic = k & 63;
            sA[m * 40 + k_l] = tf32r(w[(m * 64 + ic) * 9 + tap]);
        }
        // stage B: 32 k x 128 px im2col (zero-pad folded in)
        for (int e = tid; e < 32 * 128; e += 256) {
            int k_l = e >> 7, n = e & 127;
            int k = c * 32 + k_l;
            int tap = k >> 6, ic = k & 63;
            int yy = band + tap / 3 - 1;
            int xx = n + tap % 3 - 1;
            float v = 0.f;
            if ((unsigned)yy < (unsigned)Hc && (unsigned)xx < (unsigned)Wc)
                v = in[((size_t)(img * 64 + ic) * Hc + yy) * Wc + xx];
            sB[k_l * 136 + n] = tf32r(v);
        }
        __syncthreads();

#pragma unroll
        for (int k8 = 0; k8 < 4; ++k8) {
            wmma::fragment<wmma::matrix_a, 16, 16, 8, wmma::precision::tf32,
                           wmma::row_major> af[2];
            wmma::fragment<wmma::matrix_b, 16, 16, 8, wmma::precision::tf32,
                           wmma::row_major> bf[4];
#pragma unroll
            for (int wm = 0; wm < 2; wm++)
                wmma::load_matrix_sync(
                    af[wm], &sA[(warpM * 32 + wm * 16) * 40 + k8 * 8], 40);
#pragma unroll
            for (int wn = 0; wn < 4; wn++)
                wmma::load_matrix_sync(
                    bf[wn], &sB[(k8 * 8) * 136 + warpN * 64 + wn * 16], 136);
#pragma unroll
            for (int wm = 0; wm < 2; wm++)
#pragma unroll
                for (int wn = 0; wn < 4; wn++)
                    wmma::mma_sync(acc[wm][wn], af[wm], bf[wn], acc[wm][wn]);
        }
    }

    // store RAW: rows = channels (stride Hc*Wc), cols = pixels
#pragma unroll
    for (int wm = 0; wm < 2; wm++)
#pragma unroll
        for (int wn = 0; wn < 4; wn++) {
            int m0 = warpM * 32 + wm * 16;
            int n0 = warpN * 64 + wn * 16;
            float* p = &g_y1[((size_t)(img * 128 + m0) * Hc + band) * Wc + n0];
            wmma::store_matrix_sync(p, acc[wm][wn], Hc * Wc,
                                    wmma::mem_row_major);
        }
}

// ---------------------------------------------------------------------------
// conv2 via wmma tf32 — same skeleton as conv1_wmma_k, respecialized:
// M=32(oc) x N=256 px (two image rows), K=1152 in 36 chunks of 32.
// Warps 1(m) x 8(n); warp tile 32 x 32 (2x2 fragments).
// B staging applies relu(g_y1_raw + b1[ic]). Stores RAW accumulators.
// ---------------------------------------------------------------------------
__global__ __launch_bounds__(256, 2) void conv2_wmma_k(
    const float* __restrict__ w, const float* __restrict__ b1)
{
    __shared__ __align__(16) float sA[32 * 40];    // [m][k_l], ldm 40
    __shared__ __align__(16) float sB[32 * 264];   // [k_l][n], ldm 264

    const int tid = threadIdx.x;
    const int wid = tid >> 5;
    const int warpN = wid;              // warps 1 x 8
    const int band = blockIdx.x;        // two image rows per band
    const int img = blockIdx.y;

    wmma::fragment<wmma::accumulator, 16, 16, 8, float> acc[2][2];
#pragma unroll
    for (int wm = 0; wm < 2; wm++)
#pragma unroll
        for (int wn = 0; wn < 2; wn++) wmma::fill_fragment(acc[wm][wn], 0.f);

    for (int c = 0; c < 36; ++c) {      // K = 1152 = 36 * 32
        if (c) __syncthreads();
        // stage A: 32 m x 32 k  (k = tap*128 + ic)
        for (int e = tid; e < 32 * 32; e += 256) {
            int m = e >> 5, k_l = e & 31;
            int k = c * 32 + k_l;
            int tap = k >> 7, ic = k & 127;
            sA[m * 40 + k_l] = tf32r(w[(m * 128 + ic) * 9 + tap]);
        }
        // stage B: 32 k x 256 px im2col with relu(raw + b1) fixup
        for (int e = tid; e < 32 * 256; e += 256) {
            int k_l = e >> 8, n = e & 255;
            int k = c * 32 + k_l;
            int tap = k >> 7, ic = k & 127;
            int r = n >> 7, x = n & 127;
            int yy = band * 2 + r + tap / 3 - 1;
            int xx = x + tap % 3 - 1;
            float v = 0.f;
            if ((unsigned)yy < (unsigned)Hc && (unsigned)xx < (unsigned)Wc)
                v = fmaxf(g_y1[((size_t)(img * 128 + ic) * Hc + yy) * Wc + xx]
                          + b1[ic], 0.f);
            sB[k_l * 264 + n] = tf32r(v);
        }
        __syncthreads();

#pragma unroll
        for (int k8 = 0; k8 < 4; ++k8) {
            wmma::fragment<wmma::matrix_a, 16, 16, 8, wmma::precision::tf32,
                           wmma::row_major> af[2];
            wmma::fragment<wmma::matrix_b, 16, 16, 8, wmma::precision::tf32,
                           wmma::row_major> bf[2];
#pragma unroll
            for (int wm = 0; wm < 2; wm++)
                wmma::load_matrix_sync(af[wm], &sA[(wm * 16) * 40 + k8 * 8], 40);
#pragma unroll
            for (int wn = 0; wn < 2; wn++)
                wmma::load_matrix_sync(
                    bf[wn], &sB[(k8 * 8) * 264 + warpN * 32 + wn * 16], 264);
#pragma unroll
            for (int wm = 0; wm < 2; wm++)
#pragma unroll
                for (int wn = 0; wn < 2; wn++)
                    wmma::mma_sync(acc[wm][wn], af[wm], bf[wn], acc[wm][wn]);
        }
    }

    // store RAW
#pragma unroll
    for (int wm = 0; wm < 2; wm++)
#pragma unroll
        for (int wn = 0; wn < 2; wn++) {
            int m0 = wm * 16;
            int n0 = warpN * 32 + wn * 16;
            int r = n0 >> 7, x = n0 & 127;
            float* p = &g_y2[((size_t)(img * 32 + m0) * Hc + band * 2 + r) *
                             Wc + x];
            wmma::store_matrix_sync(p, acc[wm][wn], Hc * Wc,
                                    wmma::mem_row_major);
        }
}

// ---------------------------------------------------------------------------
// Fused bilinear x2 upsample (half-pixel, edge clamp) + 3x3 conv 32->1.
// Reads conv2 RAW: applies relu(v + b2[ic]) during staging.
// ---------------------------------------------------------------------------
__global__ __launch_bounds__(256) void upconv3_k(
    const float* __restrict__ w3, const float* __restrict__ b2,
    const float* __restrict__ b3, float* __restrict__ out)
{
    __shared__ float sv[16][10][10];
    __shared__ float su[16][18][18];
    __shared__ float sw3[288];

    const int tid = threadIdx.x;
    const int tx = tid & 15, ty = tid >> 4;
    const int tileY = (blockIdx.x >> 4) << 4;
    const int tileX = (blockIdx.x & 15) << 4;
    const int n = blockIdx.y;
    const int m0 = tileY >> 1, q0 = tileX >> 1;

    for (int e = tid; e < 288; e += 256) sw3[e] = w3[e];

    float acc = 0.f;
    for (int c0 = 0; c0 < 32; c0 += 16) {
        __syncthreads();
        for (int e = tid; e < 16 * 10 * 10; e += 256) {
            int ic = e / 100, r = (e / 10) % 10, c = e % 10;
            int gy = min(max(m0 - 1 + r, 0), Hc - 1);
            int gx = min(max(q0 - 1 + c, 0), Wc - 1);
            float v = g_y2[((size_t)(n * 32 + c0 + ic) * Hc + gy) * Wc + gx];
            sv[ic][r][c] = fmaxf(v + b2[c0 + ic], 0.f);
        }
        __syncthreads();
        for (int e = tid; e < 16 * 18 * 18; e += 256) {
            int ic = e / 324, r = (e / 18) % 18, c = e % 18;
            int tyg = tileY - 1 + r, txg = tileX - 1 + c;
            float uv = 0.f;
            if ((unsigned)tyg < 256u && (unsigned)txg < 256u) {
                int i0y, i0x; float fy, fx;
                if (tyg & 1) { i0y = tyg >> 1;       fy = 0.25f; }
                else         { i0y = (tyg >> 1) - 1; fy = 0.75f; }
                if (txg & 1) { i0x = txg >> 1;       fx = 0.25f; }
                else         { i0x = (txg >> 1) - 1; fx = 0.75f; }
                int ly = i0y - (m0 - 1), lx = i0x - (q0 - 1);
                float v00 = sv[ic][ly][lx],     v01 = sv[ic][ly][lx + 1];
                float v10 = sv[ic][ly + 1][lx], v11 = sv[ic][ly + 1][lx + 1];
                float gy1 = 1.f - fy, gx1 = 1.f - fx;
                uv = gy1 * (gx1 * v00 + fx * v01) + fy * (gx1 * v10 + fx * v11);
            }
            su[ic][r][c] = uv;
        }
        __syncthreads();
#pragma unroll
        for (int ic = 0; ic < 16; ic++)
#pragma unroll
            for (int dy = 0; dy < 3; dy++)
#pragma unroll
                for (int dx = 0; dx < 3; dx++)
                    acc = fmaf(sw3[(c0 + ic) * 9 + dy * 3 + dx],
                               su[ic][ty + dy][tx + dx], acc);
    }
    acc += b3[0];
    out[((size_t)(n * 256) + tileY + ty) * 256 + tileX + tx] = acc;
}

// ---------------------------------------------------------------------------
extern "C" void kernel_launch(void* const* d_in, const int* in_sizes, int n_in,
                              void* d_out, int out_size)
{
    const float* x  = (const float*)d_in[0];
    const float* W1 = (const float*)d_in[3];
    const float* b1 = (const float*)d_in[4];
    const float* W2 = (const float*)d_in[5];
    const float* b2 = (const float*)d_in[6];
    const float* W3 = (const float*)d_in[7];
    const float* b3 = (const float*)d_in[8];
    float* out = (float*)d_out;

    conv1_wmma_k<<<dim3(Hc, N_IMG), 256>>>(W1, x);
    conv2_wmma_k<<<dim3(Hc / 2, N_IMG), 256>>>(W2, b1);
    upconv3_k<<<dim3(256, N_IMG), 256>>>(W3, b2, b3, out);
}

// round 10
// speedup vs baseline: 1.8512x; 1.0063x over previous
#include <cuda_runtime.h>
#include <mma.h>
#include <cstdint>

using namespace nvcuda;

#define N_IMG 48
#define Hc 128
#define Wc 128

__device__ float g_y1[48u * 128u * 128u * 128u];   // conv1 POST-act, tf32-rounded
__device__ float g_y2[48u * 32u * 128u * 128u];    // conv2 RAW (pre-bias/relu)

__device__ __forceinline__ float tf32r(float v) {
    uint32_t u;
    asm("cvt.rna.tf32.f32 %0, %1;" : "=r"(u) : "f"(v));
    return __uint_as_float(u);
}
__device__ __forceinline__ uint32_t smem_u32(const void* p) {
    uint32_t a;
    asm("{ .reg .u64 t; cvta.to.shared.u64 t, %1; cvt.u32.u64 %0, t; }"
        : "=r"(a) : "l"(p));
    return a;
}
__device__ __forceinline__ void cpa4(uint32_t dst, const void* src, bool ok) {
    int sz = ok ? 4 : 0;
    asm volatile("cp.async.ca.shared.global [%0], [%1], %2, %3;"
                 :: "r"(dst), "l"(src), "n"(4), "r"(sz) : "memory");
}
__device__ __forceinline__ void cpa_commit() {
    asm volatile("cp.async.commit_group;" ::: "memory");
}
__device__ __forceinline__ void cpa_wait0() {
    asm volatile("cp.async.wait_group 0;" ::: "memory");
}

// ---------------------------------------------------------------------------
// conv1: wmma tf32 implicit GEMM, cp.async double-buffered K chunks of 16.
// CTA: M=128(oc) x N=128 px (one row), K=576 (36 chunks). Warps 4x2, 32x64.
// Post-load smem convert to tf32 (rna). Epilogue: bias+relu+tf32r via
// per-warp smem roundtrip; stores POST-activation.
// ---------------------------------------------------------------------------
__global__ __launch_bounds__(256, 2) void conv1_wmma_k(
    const float* __restrict__ w, const float* __restrict__ b1,
    const float* __restrict__ in)
{
    __shared__ __align__(16) float sA[2][128 * 24];   // [m][k_l], ldm 24
    __shared__ __align__(16) float sB[2][16 * 136];   // [k_l][n], ldm 136

    const int tid = threadIdx.x;
    const int lane = tid & 31, wid = tid >> 5;
    const int warpM = wid >> 1, warpN = wid & 1;
    const int band = blockIdx.x, img = blockIdx.y;

    const uint32_t sAu[2] = { smem_u32(sA[0]), smem_u32(sA[1]) };
    const uint32_t sBu[2] = { smem_u32(sB[0]), smem_u32(sB[1]) };

    auto issue = [&](int c, int buf) {
        for (int e = tid; e < 128 * 16; e += 256) {       // A: 8/thr
            int m = e >> 4, kl = e & 15;
            int k = c * 16 + kl;
            int tap = k >> 6, ic = k & 63;
            cpa4(sAu[buf] + (m * 24 + kl) * 4, &w[(m * 64 + ic) * 9 + tap], true);
        }
        for (int e = tid; e < 16 * 128; e += 256) {       // B: 8/thr
            int kl = e >> 7, n = e & 127;
            int k = c * 16 + kl;
            int tap = k >> 6, ic = k & 63;
            int yy = band + tap / 3 - 1;
            int xx = n + tap % 3 - 1;
            bool ok = (unsigned)yy < (unsigned)Hc && (unsigned)xx < (unsigned)Wc;
            const float* src = ok ?
                &in[((size_t)(img * 64 + ic) * Hc + yy) * Wc + xx] : in;
            cpa4(sBu[buf] + (kl * 136 + n) * 4, src, ok);
        }
        cpa_commit();
    };

    wmma::fragment<wmma::accumulator, 16, 16, 8, float> acc[2][4];
#pragma unroll
    for (int wm = 0; wm < 2; wm++)
#pragma unroll
        for (int wn = 0; wn < 4; wn++) wmma::fill_fragment(acc[wm][wn], 0.f);

    issue(0, 0);
    for (int c = 0; c < 36; ++c) {
        const int buf = c & 1;
        cpa_wait0();
        __syncthreads();
        // convert staged fp32 -> tf32 (rna) in place
        for (int e = tid; e < 128 * 16; e += 256) {
            int m = e >> 4, kl = e & 15;
            sA[buf][m * 24 + kl] = tf32r(sA[buf][m * 24 + kl]);
        }
        for (int e = tid; e < 16 * 128; e += 256) {
            int kl = e >> 7, n = e & 127;
            sB[buf][kl * 136 + n] = tf32r(sB[buf][kl * 136 + n]);
        }
        __syncthreads();
        if (c + 1 < 36) issue(c + 1, (c + 1) & 1);

#pragma unroll
        for (int k8 = 0; k8 < 2; ++k8) {
            wmma::fragment<wmma::matrix_a, 16, 16, 8, wmma::precision::tf32,
                           wmma::row_major> af[2];
            wmma::fragment<wmma::matrix_b, 16, 16, 8, wmma::precision::tf32,
                           wmma::row_major> bf[4];
#pragma unroll
            for (int wm = 0; wm < 2; wm++)
                wmma::load_matrix_sync(
                    af[wm], &sA[buf][(warpM * 32 + wm * 16) * 24 + k8 * 8], 24);
#pragma unroll
            for (int wn = 0; wn < 4; wn++)
                wmma::load_matrix_sync(
                    bf[wn], &sB[buf][(k8 * 8) * 136 + warpN * 64 + wn * 16], 136);
#pragma unroll
            for (int wm = 0; wm < 2; wm++)
#pragma unroll
                for (int wn = 0; wn < 4; wn++)
                    wmma::mma_sync(acc[wm][wn], af[wm], bf[wn], acc[wm][wn]);
        }
    }

    // epilogue: per-warp smem roundtrip -> bias + relu + tf32 round -> store
    __syncthreads();
    float* scr = &sB[0][wid * 272];
#pragma unroll
    for (int wm = 0; wm < 2; wm++)
#pragma unroll
        for (int wn = 0; wn < 4; wn++) {
            wmma::store_matrix_sync(scr, acc[wm][wn], 16, wmma::mem_row_major);
            __syncwarp();
            int m0 = warpM * 32 + wm * 16;
            int n0 = warpN * 64 + wn * 16;
#pragma unroll
            for (int e = lane; e < 256; e += 32) {
                int r = e >> 4, cc = e & 15;
                float v = tf32r(fmaxf(scr[e] + b1[m0 + r], 0.f));
                g_y1[((size_t)(img * 128 + m0 + r) * Hc + band) * Wc + n0 + cc] = v;
            }
            __syncwarp();
        }
}

// ---------------------------------------------------------------------------
// conv2: wmma tf32, cp.async double-buffered K chunks of 16.
// CTA: M=32(oc) x N=256 px (two rows), K=1152 (72 chunks). Warps 1x8, 32x32.
// B is a pure copy of pre-rounded g_y1 (no convert pass). Stores RAW.
// ---------------------------------------------------------------------------
__global__ __launch_bounds__(256, 2) void conv2_wmma_k(
    const float* __restrict__ w)
{
    __shared__ __align__(16) float sA[2][32 * 24];    // [m][k_l], ldm 24
    __shared__ __align__(16) float sB[2][16 * 264];   // [k_l][n], ldm 264

    const int tid = threadIdx.x;
    const int wid = tid >> 5;
    const int warpN = wid;
    const int band = blockIdx.x, img = blockIdx.y;

    const uint32_t sAu[2] = { smem_u32(sA[0]), smem_u32(sA[1]) };
    const uint32_t sBu[2] = { smem_u32(sB[0]), smem_u32(sB[1]) };

    auto issue = [&](int c, int buf) {
        for (int e = tid; e < 32 * 16; e += 256) {        // A: 2/thr
            int m = e >> 4, kl = e & 15;
            int k = c * 16 + kl;
            int tap = k >> 7, ic = k & 127;
            cpa4(sAu[buf] + (m * 24 + kl) * 4, &w[(m * 128 + ic) * 9 + tap], true);
        }
        for (int e = tid; e < 16 * 256; e += 256) {       // B: 16/thr
            int kl = e >> 8, n = e & 255;
            int k = c * 16 + kl;
            int tap = k >> 7, ic = k & 127;
            int r = n >> 7, x = n & 127;
            int yy = band * 2 + r + tap / 3 - 1;
            int xx = x + tap % 3 - 1;
            bool ok = (unsigned)yy < (unsigned)Hc && (unsigned)xx < (unsigned)Wc;
            const float* src = ok ?
                &g_y1[((size_t)(img * 128 + ic) * Hc + yy) * Wc + xx] : g_y1;
            cpa4(sBu[buf] + (kl * 264 + n) * 4, src, ok);
        }
        cpa_commit();
    };

    wmma::fragment<wmma::accumulator, 16, 16, 8, float> acc[2][2];
#pragma unroll
    for (int wm = 0; wm < 2; wm++)
#pragma unroll
        for (int wn = 0; wn < 2; wn++) wmma::fill_fragment(acc[wm][wn], 0.f);

    issue(0, 0);
    for (int c = 0; c < 72; ++c) {
        const int buf = c & 1;
        cpa_wait0();
        __syncthreads();
        // convert A only (B holds pre-rounded activations)
        for (int e = tid; e < 32 * 16; e += 256) {
            int m = e >> 4, kl = e & 15;
            sA[buf][m * 24 + kl] = tf32r(sA[buf][m * 24 + kl]);
        }
        __syncthreads();
        if (c + 1 < 72) issue(c + 1, (c + 1) & 1);

#pragma unroll
        for (int k8 = 0; k8 < 2; ++k8) {
            wmma::fragment<wmma::matrix_a, 16, 16, 8, wmma::precision::tf32,
                           wmma::row_major> af[2];
            wmma::fragment<wmma::matrix_b, 16, 16, 8, wmma::precision::tf32,
                           wmma::row_major> bf[2];
#pragma unroll
            for (int wm = 0; wm < 2; wm++)
                wmma::load_matrix_sync(af[wm],
                                       &sA[buf][(wm * 16) * 24 + k8 * 8], 24);
#pragma unroll
            for (int wn = 0; wn < 2; wn++)
                wmma::load_matrix_sync(
                    bf[wn], &sB[buf][(k8 * 8) * 264 + warpN * 32 + wn * 16], 264);
#pragma unroll
            for (int wm = 0; wm < 2; wm++)
#pragma unroll
                for (int wn = 0; wn < 2; wn++)
                    wmma::mma_sync(acc[wm][wn], af[wm], bf[wn], acc[wm][wn]);
        }
    }

    // store RAW
#pragma unroll
    for (int wm = 0; wm < 2; wm++)
#pragma unroll
        for (int wn = 0; wn < 2; wn++) {
            int m0 = wm * 16;
            int n0 = warpN * 32 + wn * 16;
            int r = n0 >> 7, x = n0 & 127;
            float* p = &g_y2[((size_t)(img * 32 + m0) * Hc + band * 2 + r) *
                             Wc + x];
            wmma::store_matrix_sync(p, acc[wm][wn], Hc * Wc,
                                    wmma::mem_row_major);
        }
}

// ---------------------------------------------------------------------------
// Fused bilinear x2 upsample (half-pixel, edge clamp) + 3x3 conv 32->1.
// Reads conv2 RAW: applies relu(v + b2[ic]) during staging.
// ---------------------------------------------------------------------------
__global__ __launch_bounds__(256) void upconv3_k(
    const float* __restrict__ w3, const float* __restrict__ b2,
    const float* __restrict__ b3, float* __restrict__ out)
{
    __shared__ float sv[16][10][10];
    __shared__ float su[16][18][18];
    __shared__ float sw3[288];

    const int tid = threadIdx.x;
    const int tx = tid & 15, ty = tid >> 4;
    const int tileY = (blockIdx.x >> 4) << 4;
    const int tileX = (blockIdx.x & 15) << 4;
    const int n = blockIdx.y;
    const int m0 = tileY >> 1, q0 = tileX >> 1;

    for (int e = tid; e < 288; e += 256) sw3[e] = w3[e];

    float acc = 0.f;
    for (int c0 = 0; c0 < 32; c0 += 16) {
        __syncthreads();
        for (int e = tid; e < 16 * 10 * 10; e += 256) {
            int ic = e / 100, r = (e / 10) % 10, c = e % 10;
            int gy = min(max(m0 - 1 + r, 0), Hc - 1);
            int gx = min(max(q0 - 1 + c, 0), Wc - 1);
            float v = g_y2[((size_t)(n * 32 + c0 + ic) * Hc + gy) * Wc + gx];
            sv[ic][r][c] = fmaxf(v + b2[c0 + ic], 0.f);
        }
        __syncthreads();
        for (int e = tid; e < 16 * 18 * 18; e += 256) {
            int ic = e / 324, r = (e / 18) % 18, c = e % 18;
            int tyg = tileY - 1 + r, txg = tileX - 1 + c;
            float uv = 0.f;
            if ((unsigned)tyg < 256u && (unsigned)txg < 256u) {
                int i0y, i0x; float fy, fx;
                if (tyg & 1) { i0y = tyg >> 1;       fy = 0.25f; }
                else         { i0y = (tyg >> 1) - 1; fy = 0.75f; }
                if (txg & 1) { i0x = txg >> 1;       fx = 0.25f; }
                else         { i0x = (txg >> 1) - 1; fx = 0.75f; }
                int ly = i0y - (m0 - 1), lx = i0x - (q0 - 1);
                float v00 = sv[ic][ly][lx],     v01 = sv[ic][ly][lx + 1];
                float v10 = sv[ic][ly + 1][lx], v11 = sv[ic][ly + 1][lx + 1];
                float gy1 = 1.f - fy, gx1 = 1.f - fx;
                uv = gy1 * (gx1 * v00 + fx * v01) + fy * (gx1 * v10 + fx * v11);
            }
            su[ic][r][c] = uv;
        }
        __syncthreads();
#pragma unroll
        for (int ic = 0; ic < 16; ic++)
#pragma unroll
            for (int dy = 0; dy < 3; dy++)
#pragma unroll
                for (int dx = 0; dx < 3; dx++)
                    acc = fmaf(sw3[(c0 + ic) * 9 + dy * 3 + dx],
                               su[ic][ty + dy][tx + dx], acc);
    }
    acc += b3[0];
    out[((size_t)(n * 256) + tileY + ty) * 256 + tileX + tx] = acc;
}

// ---------------------------------------------------------------------------
extern "C" void kernel_launch(void* const* d_in, const int* in_sizes, int n_in,
                              void* d_out, int out_size)
{
    const float* x  = (const float*)d_in[0];
    const float* W1 = (const float*)d_in[3];
    const float* b1 = (const float*)d_in[4];
    const float* W2 = (const float*)d_in[5];
    const float* b2 = (const float*)d_in[6];
    const float* W3 = (const float*)d_in[7];
    const float* b3 = (const float*)d_in[8];
    float* out = (float*)d_out;

    conv1_wmma_k<<<dim3(Hc, N_IMG), 256>>>(W1, b1, x);
    conv2_wmma_k<<<dim3(Hc / 2, N_IMG), 256>>>(W2);
    upconv3_k<<<dim3(256, N_IMG), 256>>>(W3, b2, b3, out);
}

// round 11
// speedup vs baseline: 2.0638x; 1.1149x over previous
#include <cuda_runtime.h>
#include <mma.h>
#include <cstdint>

using namespace nvcuda;

#define N_IMG 48
#define Hc 128
#define Wc 128

__device__ float g_y1[48u * 128u * 128u * 128u];   // conv1 POST-act, tf32-rounded
__device__ float g_y2[48u * 32u * 128u * 128u];    // conv2 RAW (pre-bias/relu)
__device__ float g_xr[48u * 64u * 128u * 128u];    // x pre-rounded to tf32
__device__ float g_w1t[576 * 128];                 // W1 tf32, [k][m]
__device__ float g_w2t[1152 * 32];                 // W2 tf32, [k][m]

__device__ __forceinline__ float tf32r(float v) {
    uint32_t u;
    asm("cvt.rna.tf32.f32 %0, %1;" : "=r"(u) : "f"(v));
    return __uint_as_float(u);
}
__device__ __forceinline__ uint32_t smem_u32(const void* p) {
    uint32_t a;
    asm("{ .reg .u64 t; cvta.to.shared.u64 t, %1; cvt.u32.u64 %0, t; }"
        : "=r"(a) : "l"(p));
    return a;
}
__device__ __forceinline__ void cpa4(uint32_t dst, const void* src, bool ok) {
    int sz = ok ? 4 : 0;
    asm volatile("cp.async.ca.shared.global [%0], [%1], %2, %3;"
                 :: "r"(dst), "l"(src), "n"(4), "r"(sz) : "memory");
}
__device__ __forceinline__ void cpa_commit() {
    asm volatile("cp.async.commit_group;" ::: "memory");
}
__device__ __forceinline__ void cpa_wait0() {
    asm volatile("cp.async.wait_group 0;" ::: "memory");
}

// ---- one-time pre-round kernels -------------------------------------------
__global__ __launch_bounds__(256) void xr_k(const float* __restrict__ x) {
    size_t i = (size_t)(blockIdx.x * 256 + threadIdx.x) * 4;
    float4 v = *(const float4*)&x[i];
    v.x = tf32r(v.x); v.y = tf32r(v.y); v.z = tf32r(v.z); v.w = tf32r(v.w);
    *(float4*)&g_xr[i] = v;
}
__global__ __launch_bounds__(256) void wt1_k(const float* __restrict__ w) {
    int idx = blockIdx.x * 256 + threadIdx.x;          // < 576*128
    int k = idx >> 7, m = idx & 127;
    int tap = k >> 6, ic = k & 63;
    g_w1t[idx] = tf32r(w[(m * 64 + ic) * 9 + tap]);
}
__global__ __launch_bounds__(256) void wt2_k(const float* __restrict__ w) {
    int idx = blockIdx.x * 256 + threadIdx.x;          // < 1152*32
    int k = idx >> 5, m = idx & 31;
    int tap = k >> 7, ic = k & 127;
    g_w2t[idx] = tf32r(w[(m * 128 + ic) * 9 + tap]);
}

// ---------------------------------------------------------------------------
// conv1: wmma tf32 implicit GEMM, cp.async double-buffered K chunks of 16.
// All staged data pre-rounded -> pure-copy staging, ONE sync per chunk.
// CTA: M=128(oc) x N=128 px (one row), K=576 (36 chunks). Warps 4x2, 32x64.
// Epilogue: bias+relu+tf32r via per-warp smem roundtrip; stores POST-act.
// ---------------------------------------------------------------------------
__global__ __launch_bounds__(256, 2) void conv1_wmma_k(
    const float* __restrict__ b1)
{
    __shared__ __align__(16) float sA[2][128 * 24];   // [m][k_l], ldm 24
    __shared__ __align__(16) float sB[2][16 * 136];   // [k_l][n], ldm 136

    const int tid = threadIdx.x;
    const int lane = tid & 31, wid = tid >> 5;
    const int warpM = wid >> 1, warpN = wid & 1;
    const int band = blockIdx.x, img = blockIdx.y;

    const uint32_t sAu[2] = { smem_u32(sA[0]), smem_u32(sA[1]) };
    const uint32_t sBu[2] = { smem_u32(sB[0]), smem_u32(sB[1]) };

    auto issue = [&](int c, int buf) {
        for (int e = tid; e < 128 * 16; e += 256) {       // A: coalesced, m fast
            int kl = e >> 7, m = e & 127;
            cpa4(sAu[buf] + (m * 24 + kl) * 4, &g_w1t[(c * 16 + kl) * 128 + m],
                 true);
        }
        for (int e = tid; e < 16 * 128; e += 256) {       // B: im2col copy
            int kl = e >> 7, n = e & 127;
            int k = c * 16 + kl;
            int tap = k >> 6, ic = k & 63;
            int yy = band + tap / 3 - 1;
            int xx = n + tap % 3 - 1;
            bool ok = (unsigned)yy < (unsigned)Hc && (unsigned)xx < (unsigned)Wc;
            const float* src = ok ?
                &g_xr[((size_t)(img * 64 + ic) * Hc + yy) * Wc + xx] : g_xr;
            cpa4(sBu[buf] + (kl * 136 + n) * 4, src, ok);
        }
        cpa_commit();
    };

    wmma::fragment<wmma::accumulator, 16, 16, 8, float> acc[2][4];
#pragma unroll
    for (int wm = 0; wm < 2; wm++)
#pragma unroll
        for (int wn = 0; wn < 4; wn++) wmma::fill_fragment(acc[wm][wn], 0.f);

    issue(0, 0);
    for (int c = 0; c < 36; ++c) {
        const int buf = c & 1;
        cpa_wait0();
        __syncthreads();
        if (c + 1 < 36) issue(c + 1, (c + 1) & 1);

#pragma unroll
        for (int k8 = 0; k8 < 2; ++k8) {
            wmma::fragment<wmma::matrix_a, 16, 16, 8, wmma::precision::tf32,
                           wmma::row_major> af[2];
            wmma::fragment<wmma::matrix_b, 16, 16, 8, wmma::precision::tf32,
                           wmma::row_major> bf[4];
#pragma unroll
            for (int wm = 0; wm < 2; wm++)
                wmma::load_matrix_sync(
                    af[wm], &sA[buf][(warpM * 32 + wm * 16) * 24 + k8 * 8], 24);
#pragma unroll
            for (int wn = 0; wn < 4; wn++)
                wmma::load_matrix_sync(
                    bf[wn], &sB[buf][(k8 * 8) * 136 + warpN * 64 + wn * 16], 136);
#pragma unroll
            for (int wm = 0; wm < 2; wm++)
#pragma unroll
                for (int wn = 0; wn < 4; wn++)
                    wmma::mma_sync(acc[wm][wn], af[wm], bf[wn], acc[wm][wn]);
        }
    }

    // epilogue: per-warp smem roundtrip -> bias + relu + tf32 round -> store
    __syncthreads();
    float* scr = &sB[0][wid * 272];
#pragma unroll
    for (int wm = 0; wm < 2; wm++)
#pragma unroll
        for (int wn = 0; wn < 4; wn++) {
            wmma::store_matrix_sync(scr, acc[wm][wn], 16, wmma::mem_row_major);
            __syncwarp();
            int m0 = warpM * 32 + wm * 16;
            int n0 = warpN * 64 + wn * 16;
#pragma unroll
            for (int e = lane; e < 256; e += 32) {
                int r = e >> 4, cc = e & 15;
                float v = tf32r(fmaxf(scr[e] + b1[m0 + r], 0.f));
                g_y1[((size_t)(img * 128 + m0 + r) * Hc + band) * Wc + n0 + cc] = v;
            }
            __syncwarp();
        }
}

// ---------------------------------------------------------------------------
// conv2: wmma tf32, cp.async double-buffered K chunks of 16, pure-copy A+B.
// CTA: M=32(oc) x N=256 px (two rows), K=1152 (72 chunks). Warps 1x8, 32x32.
// Stores RAW accumulators.
// ---------------------------------------------------------------------------
__global__ __launch_bounds__(256, 2) void conv2_wmma_k()
{
    __shared__ __align__(16) float sA[2][32 * 24];    // [m][k_l], ldm 24
    __shared__ __align__(16) float sB[2][16 * 264];   // [k_l][n], ldm 264

    const int tid = threadIdx.x;
    const int wid = tid >> 5;
    const int warpN = wid;
    const int band = blockIdx.x, img = blockIdx.y;

    const uint32_t sAu[2] = { smem_u32(sA[0]), smem_u32(sA[1]) };
    const uint32_t sBu[2] = { smem_u32(sB[0]), smem_u32(sB[1]) };

    auto issue = [&](int c, int buf) {
        for (int e = tid; e < 32 * 16; e += 256) {        // A: coalesced, m fast
            int kl = e >> 5, m = e & 31;
            cpa4(sAu[buf] + (m * 24 + kl) * 4, &g_w2t[(c * 16 + kl) * 32 + m],
                 true);
        }
        for (int e = tid; e < 16 * 256; e += 256) {       // B: im2col copy
            int kl = e >> 8, n = e & 255;
            int k = c * 16 + kl;
            int tap = k >> 7, ic = k & 127;
            int r = n >> 7, x = n & 127;
            int yy = band * 2 + r + tap / 3 - 1;
            int xx = x + tap % 3 - 1;
            bool ok = (unsigned)yy < (unsigned)Hc && (unsigned)xx < (unsigned)Wc;
            const float* src = ok ?
                &g_y1[((size_t)(img * 128 + ic) * Hc + yy) * Wc + xx] : g_y1;
            cpa4(sBu[buf] + (kl * 264 + n) * 4, src, ok);
        }
        cpa_commit();
    };

    wmma::fragment<wmma::accumulator, 16, 16, 8, float> acc[2][2];
#pragma unroll
    for (int wm = 0; wm < 2; wm++)
#pragma unroll
        for (int wn = 0; wn < 2; wn++) wmma::fill_fragment(acc[wm][wn], 0.f);

    issue(0, 0);
    for (int c = 0; c < 72; ++c) {
        const int buf = c & 1;
        cpa_wait0();
        __syncthreads();
        if (c + 1 < 72) issue(c + 1, (c + 1) & 1);

#pragma unroll
        for (int k8 = 0; k8 < 2; ++k8) {
            wmma::fragment<wmma::matrix_a, 16, 16, 8, wmma::precision::tf32,
                           wmma::row_major> af[2];
            wmma::fragment<wmma::matrix_b, 16, 16, 8, wmma::precision::tf32,
                           wmma::row_major> bf[2];
#pragma unroll
            for (int wm = 0; wm < 2; wm++)
                wmma::load_matrix_sync(af[wm],
                                       &sA[buf][(wm * 16) * 24 + k8 * 8], 24);
#pragma unroll
            for (int wn = 0; wn < 2; wn++)
                wmma::load_matrix_sync(
                    bf[wn], &sB[buf][(k8 * 8) * 264 + warpN * 32 + wn * 16], 264);
#pragma unroll
            for (int wm = 0; wm < 2; wm++)
#pragma unroll
                for (int wn = 0; wn < 2; wn++)
                    wmma::mma_sync(acc[wm][wn], af[wm], bf[wn], acc[wm][wn]);
        }
    }

    // store RAW
#pragma unroll
    for (int wm = 0; wm < 2; wm++)
#pragma unroll
        for (int wn = 0; wn < 2; wn++) {
            int m0 = wm * 16;
            int n0 = warpN * 32 + wn * 16;
            int r = n0 >> 7, x = n0 & 127;
            float* p = &g_y2[((size_t)(img * 32 + m0) * Hc + band * 2 + r) *
                             Wc + x];
            wmma::store_matrix_sync(p, acc[wm][wn], Hc * Wc,
                                    wmma::mem_row_major);
        }
}

// ---------------------------------------------------------------------------
// Fused bilinear x2 upsample (half-pixel, edge clamp) + 3x3 conv 32->1.
// Reads conv2 RAW: applies relu(v + b2[ic]) during staging.
// ---------------------------------------------------------------------------
__global__ __launch_bounds__(256) void upconv3_k(
    const float* __restrict__ w3, const float* __restrict__ b2,
    const float* __restrict__ b3, float* __restrict__ out)
{
    __shared__ float sv[16][10][10];
    __shared__ float su[16][18][18];
    __shared__ float sw3[288];

    const int tid = threadIdx.x;
    const int tx = tid & 15, ty = tid >> 4;
    const int tileY = (blockIdx.x >> 4) << 4;
    const int tileX = (blockIdx.x & 15) << 4;
    const int n = blockIdx.y;
    const int m0 = tileY >> 1, q0 = tileX >> 1;

    for (int e = tid; e < 288; e += 256) sw3[e] = w3[e];

    float acc = 0.f;
    for (int c0 = 0; c0 < 32; c0 += 16) {
        __syncthreads();
        for (int e = tid; e < 16 * 10 * 10; e += 256) {
            int ic = e / 100, r = (e / 10) % 10, c = e % 10;
            int gy = min(max(m0 - 1 + r, 0), Hc - 1);
            int gx = min(max(q0 - 1 + c, 0), Wc - 1);
            float v = g_y2[((size_t)(n * 32 + c0 + ic) * Hc + gy) * Wc + gx];
            sv[ic][r][c] = fmaxf(v + b2[c0 + ic], 0.f);
        }
        __syncthreads();
        for (int e = tid; e < 16 * 18 * 18; e += 256) {
            int ic = e / 324, r = (e / 18) % 18, c = e % 18;
            int tyg = tileY - 1 + r, txg = tileX - 1 + c;
            float uv = 0.f;
            if ((unsigned)tyg < 256u && (unsigned)txg < 256u) {
                int i0y, i0x; float fy, fx;
                if (tyg & 1) { i0y = tyg >> 1;       fy = 0.25f; }
                else         { i0y = (tyg >> 1) - 1; fy = 0.75f; }
                if (txg & 1) { i0x = txg >> 1;       fx = 0.25f; }
                else         { i0x = (txg >> 1) - 1; fx = 0.75f; }
                int ly = i0y - (m0 - 1), lx = i0x - (q0 - 1);
                float v00 = sv[ic][ly][lx],     v01 = sv[ic][ly][lx + 1];
                float v10 = sv[ic][ly + 1][lx], v11 = sv[ic][ly + 1][lx + 1];
                float gy1 = 1.f - fy, gx1 = 1.f - fx;
                uv = gy1 * (gx1 * v00 + fx * v01) + fy * (gx1 * v10 + fx * v11);
            }
            su[ic][r][c] = uv;
        }
        __syncthreads();
#pragma unroll
        for (int ic = 0; ic < 16; ic++)
#pragma unroll
            for (int dy = 0; dy < 3; dy++)
#pragma unroll
                for (int dx = 0; dx < 3; dx++)
                    acc = fmaf(sw3[(c0 + ic) * 9 + dy * 3 + dx],
                               su[ic][ty + dy][tx + dx], acc);
    }
    acc += b3[0];
    out[((size_t)(n * 256) + tileY + ty) * 256 + tileX + tx] = acc;
}

// ---------------------------------------------------------------------------
extern "C" void kernel_launch(void* const* d_in, const int* in_sizes, int n_in,
                              void* d_out, int out_size)
{
    const float* x  = (const float*)d_in[0];
    const float* W1 = (const float*)d_in[3];
    const float* b1 = (const float*)d_in[4];
    const float* W2 = (const float*)d_in[5];
    const float* b2 = (const float*)d_in[6];
    const float* W3 = (const float*)d_in[7];
    const float* b3 = (const float*)d_in[8];
    float* out = (float*)d_out;

    xr_k<<<48u * 64u * 128u * 128u / (256 * 4), 256>>>(x);
    wt1_k<<<576 * 128 / 256, 256>>>(W1);
    wt2_k<<<1152 * 32 / 256, 256>>>(W2);

    conv1_wmma_k<<<dim3(Hc, N_IMG), 256>>>(b1);
    conv2_wmma_k<<<dim3(Hc / 2, N_IMG), 256>>>();
    upconv3_k<<<dim3(256, N_IMG), 256>>>(W3, b2, b3, out);
}

// round 12
// speedup vs baseline: 2.6698x; 1.2936x over previous
#include <cuda_runtime.h>
#include <mma.h>
#include <cstdint>

using namespace nvcuda;

#define N_IMG 48
#define Hc 128
#define Wc 128

__device__ float g_y1[48u * 128u * 128u * 128u];   // conv1 POST-act tf32, NHWC [img][y][x][128]
__device__ float g_y2[48u * 32u * 128u * 128u];    // conv2 RAW, NCHW
__device__ float g_xr[48u * 128u * 128u * 64u];    // x tf32-rounded, NHWC [img][y][x][64]
__device__ float g_w1t[36 * 128 * 16];             // W1 tf32 chunk image [c][m][kl]
__device__ float g_w2t[72 * 32 * 16];              // W2 tf32 chunk image [c][m][kl]

__device__ __forceinline__ float tf32r(float v) {
    uint32_t u;
    asm("cvt.rna.tf32.f32 %0, %1;" : "=r"(u) : "f"(v));
    return __uint_as_float(u);
}
__device__ __forceinline__ uint32_t smem_u32(const void* p) {
    uint32_t a;
    asm("{ .reg .u64 t; cvta.to.shared.u64 t, %1; cvt.u32.u64 %0, t; }"
        : "=r"(a) : "l"(p));
    return a;
}
__device__ __forceinline__ void cpa16(uint32_t dst, const void* src, bool ok) {
    int sz = ok ? 16 : 0;
    asm volatile("cp.async.cg.shared.global [%0], [%1], 16, %2;"
                 :: "r"(dst), "l"(src), "r"(sz) : "memory");
}
__device__ __forceinline__ void cpa_commit() {
    asm volatile("cp.async.commit_group;" ::: "memory");
}
__device__ __forceinline__ void cpa_wait0() {
    asm volatile("cp.async.wait_group 0;" ::: "memory");
}

// ---- prep: x NCHW -> g_xr NHWC (tf32-rounded), smem-tiled transpose -------
__global__ __launch_bounds__(256) void xt_k(const float* __restrict__ x) {
    __shared__ float t[64][129];
    const int y = blockIdx.x, img = blockIdx.y;
    for (int e = threadIdx.x; e < 64 * 128; e += 256) {
        int ic = e >> 7, px = e & 127;
        t[ic][px] = tf32r(x[((size_t)(img * 64 + ic) * Hc + y) * Wc + px]);
    }
    __syncthreads();
    float* dst = &g_xr[(size_t)(img * Hc + y) * Wc * 64];
    for (int e = threadIdx.x; e < 2048; e += 256) {
        int px = e >> 4, icj = (e & 15) << 2;
        float4 v = { t[icj][px], t[icj + 1][px], t[icj + 2][px], t[icj + 3][px] };
        *(float4*)&dst[px * 64 + icj] = v;
    }
}
// ---- prep: weights -> chunk images [c][m][kl], k = tap*IC + ic ------------
__global__ __launch_bounds__(256) void wt1_k(const float* __restrict__ w) {
    int idx = blockIdx.x * 256 + threadIdx.x;          // < 36*128*16
    int kl = idx & 15, m = (idx >> 4) & 127, c = idx >> 11;
    int k = c * 16 + kl;
    int tap = k >> 6, ic = k & 63;
    g_w1t[idx] = tf32r(w[(m * 64 + ic) * 9 + tap]);
}
__global__ __launch_bounds__(256) void wt2_k(const float* __restrict__ w) {
    int idx = blockIdx.x * 256 + threadIdx.x;          // < 72*32*16
    int kl = idx & 15, m = (idx >> 4) & 31, c = idx >> 9;
    int k = c * 16 + kl;
    int tap = k >> 7, ic = k & 127;
    g_w2t[idx] = tf32r(w[(m * 128 + ic) * 9 + tap]);
}

// ---------------------------------------------------------------------------
// conv1: wmma tf32, cp.async(16B) double-buffered K chunks of 16.
// CTA: M=128 x N=128 px (one row). Warps 4x2, warp 32x64. A row_major from
// chunk image (ldm 16); B col_major [n][k] from NHWC (ldm 28). Chunk c:
// tap = c>>2 (ky,kx), channels ic0=(c&3)*16. Epilogue: bias+relu+tf32r,
// NHWC float4 stores.
// ---------------------------------------------------------------------------
__global__ __launch_bounds__(256, 2) void conv1_wmma_k(
    const float* __restrict__ b1)
{
    __shared__ __align__(16) float sA[2][128 * 16];   // [m][kl], ldm 16
    __shared__ __align__(16) float sB[2][128 * 28];   // [n][kl], ldm 28

    const int tid = threadIdx.x;
    const int lane = tid & 31, wid = tid >> 5;
    const int warpM = wid >> 1, warpN = wid & 1;
    const int band = blockIdx.x, img = blockIdx.y;

    const uint32_t sAu[2] = { smem_u32(sA[0]), smem_u32(sA[1]) };
    const uint32_t sBu[2] = { smem_u32(sB[0]), smem_u32(sB[1]) };

    auto issue = [&](int c, int buf) {
        const int tap = c >> 2, ic0 = (c & 3) << 4;
        const int ky = tap / 3, kx = tap % 3;
        const int yy = band + ky - 1;
        const bool yok = (unsigned)yy < (unsigned)Hc;
        for (int e = tid; e < 512; e += 256) {        // A: [m][kl] contiguous
            int m = e >> 2, j = (e & 3) << 2;
            cpa16(sAu[buf] + (m * 16 + j) * 4,
                  &g_w1t[(c * 128 + m) * 16 + j], true);
        }
        for (int e = tid; e < 512; e += 256) {        // B: 16 ch of one pixel
            int n = e >> 2, j = (e & 3) << 2;
            int xx = n + kx - 1;
            bool ok = yok && (unsigned)xx < (unsigned)Wc;
            const float* src = ok ?
                &g_xr[((size_t)(img * Hc + yy) * Wc + xx) * 64 + ic0 + j] : g_xr;
            cpa16(sBu[buf] + (n * 28 + j) * 4, src, ok);
        }
        cpa_commit();
    };

    wmma::fragment<wmma::accumulator, 16, 16, 8, float> acc[2][4];
#pragma unroll
    for (int wm = 0; wm < 2; wm++)
#pragma unroll
        for (int wn = 0; wn < 4; wn++) wmma::fill_fragment(acc[wm][wn], 0.f);

    issue(0, 0);
    for (int c = 0; c < 36; ++c) {
        const int buf = c & 1;
        cpa_wait0();
        __syncthreads();
        if (c + 1 < 36) issue(c + 1, (c + 1) & 1);

#pragma unroll
        for (int k8 = 0; k8 < 2; ++k8) {
            wmma::fragment<wmma::matrix_a, 16, 16, 8, wmma::precision::tf32,
                           wmma::row_major> af[2];
            wmma::fragment<wmma::matrix_b, 16, 16, 8, wmma::precision::tf32,
                           wmma::col_major> bf[4];
#pragma unroll
            for (int wm = 0; wm < 2; wm++)
                wmma::load_matrix_sync(
                    af[wm], &sA[buf][(warpM * 32 + wm * 16) * 16 + k8 * 8], 16);
#pragma unroll
            for (int wn = 0; wn < 4; wn++)
                wmma::load_matrix_sync(
                    bf[wn], &sB[buf][(warpN * 64 + wn * 16) * 28 + k8 * 8], 28);
#pragma unroll
            for (int wm = 0; wm < 2; wm++)
#pragma unroll
                for (int wn = 0; wn < 4; wn++)
                    wmma::mma_sync(acc[wm][wn], af[wm], bf[wn], acc[wm][wn]);
        }
    }

    // epilogue: bias+relu+tf32r, NHWC channel-packed float4 stores
    __syncthreads();
    float* scr = &sB[0][wid * 272];
    const int px = lane >> 1, half = lane & 1;
#pragma unroll
    for (int wm = 0; wm < 2; wm++)
#pragma unroll
        for (int wn = 0; wn < 4; wn++) {
            wmma::store_matrix_sync(scr, acc[wm][wn], 16, wmma::mem_row_major);
            __syncwarp();
            int m0 = warpM * 32 + wm * 16 + half * 8;
            int n0 = warpN * 64 + wn * 16;
            float vv[8];
#pragma unroll
            for (int j = 0; j < 8; j++)
                vv[j] = tf32r(fmaxf(scr[(half * 8 + j) * 16 + px] + b1[m0 + j],
                                    0.f));
            float* dp = &g_y1[((size_t)(img * Hc + band) * Wc + n0 + px) * 128 + m0];
            *(float4*)dp = make_float4(vv[0], vv[1], vv[2], vv[3]);
            *(float4*)(dp + 4) = make_float4(vv[4], vv[5], vv[6], vv[7]);
            __syncwarp();
        }
}

// ---------------------------------------------------------------------------
// conv2: wmma tf32, cp.async(16B) double-buffered K chunks of 16.
// CTA: M=32 x N=128 px (one row). Warps 1x8, warp 32x16. B from g_y1 NHWC.
// Chunk c: tap = c>>3, ic0 = (c&7)*16. Stores RAW accumulators (NCHW).
// ---------------------------------------------------------------------------
__global__ __launch_bounds__(256, 2) void conv2_wmma_k()
{
    __shared__ __align__(16) float sA[2][32 * 16];    // [m][kl], ldm 16
    __shared__ __align__(16) float sB[2][128 * 28];   // [n][kl], ldm 28

    const int tid = threadIdx.x;
    const int wid = tid >> 5;
    const int n0 = wid << 4;            // warp pixel base
    const int band = blockIdx.x, img = blockIdx.y;

    const uint32_t sAu[2] = { smem_u32(sA[0]), smem_u32(sA[1]) };
    const uint32_t sBu[2] = { smem_u32(sB[0]), smem_u32(sB[1]) };

    auto issue = [&](int c, int buf) {
        const int tap = c >> 3, ic0 = (c & 7) << 4;
        const int ky = tap / 3, kx = tap % 3;
        const int yy = band + ky - 1;
        const bool yok = (unsigned)yy < (unsigned)Hc;
        if (tid < 128) {                              // A: 32m x 16kl
            int m = tid >> 2, j = (tid & 3) << 2;
            cpa16(sAu[buf] + (m * 16 + j) * 4,
                  &g_w2t[(c * 32 + m) * 16 + j], true);
        }
        for (int e = tid; e < 512; e += 256) {        // B: 16 ch of one pixel
            int n = e >> 2, j = (e & 3) << 2;
            int xx = n + kx - 1;
            bool ok = yok && (unsigned)xx < (unsigned)Wc;
            const float* src = ok ?
                &g_y1[((size_t)(img * Hc + yy) * Wc + xx) * 128 + ic0 + j] : g_y1;
            cpa16(sBu[buf] + (n * 28 + j) * 4, src, ok);
        }
        cpa_commit();
    };

    wmma::fragment<wmma::accumulator, 16, 16, 8, float> acc[2];
    wmma::fill_fragment(acc[0], 0.f);
    wmma::fill_fragment(acc[1], 0.f);

    issue(0, 0);
    for (int c = 0; c < 72; ++c) {
        const int buf = c & 1;
        cpa_wait0();
        __syncthreads();
        if (c + 1 < 72) issue(c + 1, (c + 1) & 1);

#pragma unroll
        for (int k8 = 0; k8 < 2; ++k8) {
            wmma::fragment<wmma::matrix_a, 16, 16, 8, wmma::precision::tf32,
                           wmma::row_major> af[2];
            wmma::fragment<wmma::matrix_b, 16, 16, 8, wmma::precision::tf32,
                           wmma::col_major> bf;
#pragma unroll
            for (int wm = 0; wm < 2; wm++)
                wmma::load_matrix_sync(af[wm],
                                       &sA[buf][(wm * 16) * 16 + k8 * 8], 16);
            wmma::load_matrix_sync(bf, &sB[buf][n0 * 28 + k8 * 8], 28);
            wmma::mma_sync(acc[0], af[0], bf, acc[0]);
            wmma::mma_sync(acc[1], af[1], bf, acc[1]);
        }
    }

    // store RAW (NCHW)
#pragma unroll
    for (int wm = 0; wm < 2; wm++) {
        float* p = &g_y2[((size_t)(img * 32 + wm * 16) * Hc + band) * Wc + n0];
        wmma::store_matrix_sync(p, acc[wm], Hc * Wc, wmma::mem_row_major);
    }
}

// ---------------------------------------------------------------------------
// Fused bilinear x2 upsample (half-pixel, edge clamp) + 3x3 conv 32->1.
// Reads conv2 RAW: applies relu(v + b2[ic]) during staging.
// ---------------------------------------------------------------------------
__global__ __launch_bounds__(256) void upconv3_k(
    const float* __restrict__ w3, const float* __restrict__ b2,
    const float* __restrict__ b3, float* __restrict__ out)
{
    __shared__ float sv[16][10][10];
    __shared__ float su[16][18][18];
    __shared__ float sw3[288];

    const int tid = threadIdx.x;
    const int tx = tid & 15, ty = tid >> 4;
    const int tileY = (blockIdx.x >> 4) << 4;
    const int tileX = (blockIdx.x & 15) << 4;
    const int n = blockIdx.y;
    const int m0 = tileY >> 1, q0 = tileX >> 1;

    for (int e = tid; e < 288; e += 256) sw3[e] = w3[e];

    float acc = 0.f;
    for (int c0 = 0; c0 < 32; c0 += 16) {
        __syncthreads();
        for (int e = tid; e < 16 * 10 * 10; e += 256) {
            int ic = e / 100, r = (e / 10) % 10, c = e % 10;
            int gy = min(max(m0 - 1 + r, 0), Hc - 1);
            int gx = min(max(q0 - 1 + c, 0), Wc - 1);
            float v = g_y2[((size_t)(n * 32 + c0 + ic) * Hc + gy) * Wc + gx];
            sv[ic][r][c] = fmaxf(v + b2[c0 + ic], 0.f);
        }
        __syncthreads();
        for (int e = tid; e < 16 * 18 * 18; e += 256) {
            int ic = e / 324, r = (e / 18) % 18, c = e % 18;
            int tyg = tileY - 1 + r, txg = tileX - 1 + c;
            float uv = 0.f;
            if ((unsigned)tyg < 256u && (unsigned)txg < 256u) {
                int i0y, i0x; float fy, fx;
                if (tyg & 1) { i0y = tyg >> 1;       fy = 0.25f; }
                else         { i0y = (tyg >> 1) - 1; fy = 0.75f; }
                if (txg & 1) { i0x = txg >> 1;       fx = 0.25f; }
                else         { i0x = (txg >> 1) - 1; fx = 0.75f; }
                int ly = i0y - (m0 - 1), lx = i0x - (q0 - 1);
                float v00 = sv[ic][ly][lx],     v01 = sv[ic][ly][lx + 1];
                float v10 = sv[ic][ly + 1][lx], v11 = sv[ic][ly + 1][lx + 1];
                float gy1 = 1.f - fy, gx1 = 1.f - fx;
                uv = gy1 * (gx1 * v00 + fx * v01) + fy * (gx1 * v10 + fx * v11);
            }
            su[ic][r][c] = uv;
        }
        __syncthreads();
#pragma unroll
        for (int ic = 0; ic < 16; ic++)
#pragma unroll
            for (int dy = 0; dy < 3; dy++)
#pragma unroll
                for (int dx = 0; dx < 3; dx++)
                    acc = fmaf(sw3[(c0 + ic) * 9 + dy * 3 + dx],
                               su[ic][ty + dy][tx + dx], acc);
    }
    acc += b3[0];
    out[((size_t)(n * 256) + tileY + ty) * 256 + tileX + tx] = acc;
}

// ---------------------------------------------------------------------------
extern "C" void kernel_launch(void* const* d_in, const int* in_sizes, int n_in,
                              void* d_out, int out_size)
{
    const float* x  = (const float*)d_in[0];
    const float* W1 = (const float*)d_in[3];
    const float* b1 = (const float*)d_in[4];
    const float* W2 = (const float*)d_in[5];
    const float* b2 = (const float*)d_in[6];
    const float* W3 = (const float*)d_in[7];
    const float* b3 = (const float*)d_in[8];
    float* out = (float*)d_out;

    xt_k<<<dim3(Hc, N_IMG), 256>>>(x);
    wt1_k<<<36 * 128 * 16 / 256, 256>>>(W1);
    wt2_k<<<72 * 32 * 16 / 256, 256>>>(W2);

    conv1_wmma_k<<<dim3(Hc, N_IMG), 256>>>(b1);
    conv2_wmma_k<<<dim3(Hc, N_IMG), 256>>>();
    upconv3_k<<<dim3(256, N_IMG), 256>>>(W3, b2, b3, out);
}

// round 13
// speedup vs baseline: 3.1320x; 1.1731x over previous
#include <cuda_runtime.h>
#include <mma.h>
#include <cstdint>

using namespace nvcuda;

#define N_IMG 48
#define Hc 128
#define Wc 128

__device__ float g_y1[48u * 128u * 128u * 128u];   // conv1 POST-act tf32, NHWC
__device__ float g_y2[48u * 32u * 128u * 128u];    // conv2 RAW, NCHW
__device__ float g_xr[48u * 128u * 128u * 64u];    // x tf32, NHWC
__device__ float g_w1t[36 * 128 * 16];             // W1 chunk image [c][m][kl]
__device__ float g_w2t[16 * 9 * 32 * 8];           // W2 image [cc][tap][m][j]

__device__ __forceinline__ float tf32r(float v) {
    uint32_t u;
    asm("cvt.rna.tf32.f32 %0, %1;" : "=r"(u) : "f"(v));
    return __uint_as_float(u);
}
__device__ __forceinline__ uint32_t smem_u32(const void* p) {
    uint32_t a;
    asm("{ .reg .u64 t; cvta.to.shared.u64 t, %1; cvt.u32.u64 %0, t; }"
        : "=r"(a) : "l"(p));
    return a;
}
__device__ __forceinline__ void cpa16(uint32_t dst, const void* src, bool ok) {
    int sz = ok ? 16 : 0;
    asm volatile("cp.async.cg.shared.global [%0], [%1], 16, %2;"
                 :: "r"(dst), "l"(src), "r"(sz) : "memory");
}
__device__ __forceinline__ void cpa_commit() {
    asm volatile("cp.async.commit_group;" ::: "memory");
}
__device__ __forceinline__ void cpa_wait0() {
    asm volatile("cp.async.wait_group 0;" ::: "memory");
}

// ---- prep: x NCHW -> g_xr NHWC (tf32-rounded) -----------------------------
__global__ __launch_bounds__(256) void xt_k(const float* __restrict__ x) {
    __shared__ float t[64][129];
    const int y = blockIdx.x, img = blockIdx.y;
    for (int e = threadIdx.x; e < 64 * 128; e += 256) {
        int ic = e >> 7, px = e & 127;
        t[ic][px] = tf32r(x[((size_t)(img * 64 + ic) * Hc + y) * Wc + px]);
    }
    __syncthreads();
    float* dst = &g_xr[(size_t)(img * Hc + y) * Wc * 64];
    for (int e = threadIdx.x; e < 2048; e += 256) {
        int px = e >> 4, icj = (e & 15) << 2;
        float4 v = { t[icj][px], t[icj + 1][px], t[icj + 2][px], t[icj + 3][px] };
        *(float4*)&dst[px * 64 + icj] = v;
    }
}
// ---- prep: weight images ---------------------------------------------------
__global__ __launch_bounds__(256) void wt1_k(const float* __restrict__ w) {
    int idx = blockIdx.x * 256 + threadIdx.x;          // < 36*128*16
    int kl = idx & 15, m = (idx >> 4) & 127, c = idx >> 11;
    int k = c * 16 + kl;
    int tap = k >> 6, ic = k & 63;
    g_w1t[idx] = tf32r(w[(m * 64 + ic) * 9 + tap]);
}
__global__ __launch_bounds__(256) void wt2_k(const float* __restrict__ w) {
    int idx = blockIdx.x * 256 + threadIdx.x;          // < 16*9*32*8
    int j = idx & 7, m = (idx >> 3) & 31;
    int u = idx >> 8, tap = u % 9, cc = u / 9;
    int ic = cc * 8 + j;
    g_w2t[idx] = tf32r(w[(m * 128 + ic) * 9 + tap]);
}

// ---------------------------------------------------------------------------
// conv1: unchanged from R12 (proven). wmma tf32, cp.async(16B) double-buffer.
// ---------------------------------------------------------------------------
__global__ __launch_bounds__(256, 2) void conv1_wmma_k(
    const float* __restrict__ b1)
{
    __shared__ __align__(16) float sA[2][128 * 16];   // [m][kl], ldm 16
    __shared__ __align__(16) float sB[2][128 * 28];   // [n][kl], ldm 28

    const int tid = threadIdx.x;
    const int lane = tid & 31, wid = tid >> 5;
    const int warpM = wid >> 1, warpN = wid & 1;
    const int band = blockIdx.x, img = blockIdx.y;

    const uint32_t sAu[2] = { smem_u32(sA[0]), smem_u32(sA[1]) };
    const uint32_t sBu[2] = { smem_u32(sB[0]), smem_u32(sB[1]) };

    auto issue = [&](int c, int buf) {
        const int tap = c >> 2, ic0 = (c & 3) << 4;
        const int ky = tap / 3, kx = tap % 3;
        const int yy = band + ky - 1;
        const bool yok = (unsigned)yy < (unsigned)Hc;
        for (int e = tid; e < 512; e += 256) {
            int m = e >> 2, j = (e & 3) << 2;
            cpa16(sAu[buf] + (m * 16 + j) * 4,
                  &g_w1t[(c * 128 + m) * 16 + j], true);
        }
        for (int e = tid; e < 512; e += 256) {
            int n = e >> 2, j = (e & 3) << 2;
            int xx = n + kx - 1;
            bool ok = yok && (unsigned)xx < (unsigned)Wc;
            const float* src = ok ?
                &g_xr[((size_t)(img * Hc + yy) * Wc + xx) * 64 + ic0 + j] : g_xr;
            cpa16(sBu[buf] + (n * 28 + j) * 4, src, ok);
        }
        cpa_commit();
    };

    wmma::fragment<wmma::accumulator, 16, 16, 8, float> acc[2][4];
#pragma unroll
    for (int wm = 0; wm < 2; wm++)
#pragma unroll
        for (int wn = 0; wn < 4; wn++) wmma::fill_fragment(acc[wm][wn], 0.f);

    issue(0, 0);
    for (int c = 0; c < 36; ++c) {
        const int buf = c & 1;
        cpa_wait0();
        __syncthreads();
        if (c + 1 < 36) issue(c + 1, (c + 1) & 1);

#pragma unroll
        for (int k8 = 0; k8 < 2; ++k8) {
            wmma::fragment<wmma::matrix_a, 16, 16, 8, wmma::precision::tf32,
                           wmma::row_major> af[2];
            wmma::fragment<wmma::matrix_b, 16, 16, 8, wmma::precision::tf32,
                           wmma::col_major> bf[4];
#pragma unroll
            for (int wm = 0; wm < 2; wm++)
                wmma::load_matrix_sync(
                    af[wm], &sA[buf][(warpM * 32 + wm * 16) * 16 + k8 * 8], 16);
#pragma unroll
            for (int wn = 0; wn < 4; wn++)
                wmma::load_matrix_sync(
                    bf[wn], &sB[buf][(warpN * 64 + wn * 16) * 28 + k8 * 8], 28);
#pragma unroll
            for (int wm = 0; wm < 2; wm++)
#pragma unroll
                for (int wn = 0; wn < 4; wn++)
                    wmma::mma_sync(acc[wm][wn], af[wm], bf[wn], acc[wm][wn]);
        }
    }

    __syncthreads();
    float* scr = &sB[0][wid * 272];
    const int px = lane >> 1, half = lane & 1;
#pragma unroll
    for (int wm = 0; wm < 2; wm++)
#pragma unroll
        for (int wn = 0; wn < 4; wn++) {
            wmma::store_matrix_sync(scr, acc[wm][wn], 16, wmma::mem_row_major);
            __syncwarp();
            int m0 = warpM * 32 + wm * 16 + half * 8;
            int n0 = warpN * 64 + wn * 16;
            float vv[8];
#pragma unroll
            for (int j = 0; j < 8; j++)
                vv[j] = tf32r(fmaxf(scr[(half * 8 + j) * 16 + px] + b1[m0 + j],
                                    0.f));
            float* dp = &g_y1[((size_t)(img * Hc + band) * Wc + n0 + px) * 128 + m0];
            *(float4*)dp = make_float4(vv[0], vv[1], vv[2], vv[3]);
            *(float4*)(dp + 4) = make_float4(vv[4], vv[5], vv[6], vv[7]);
            __syncwarp();
        }
}

// ---------------------------------------------------------------------------
// conv2 v2: tap-reuse. CTA = 4 rows x 128 px x 32 oc. 16 ic-chunks of 8 ch.
// Per chunk: stage 6 input rows x 130 px x 8 ch (halo+pad) + A[tap][m][8];
// then 9 taps read B via pure smem offsets (9x staging cut).
// B px-stride 12 -> col_major fragment loads conflict-free. Stores RAW NCHW.
// ---------------------------------------------------------------------------
__global__ __launch_bounds__(256, 2) void conv2_wmma_k()
{
    __shared__ __align__(16) float sA[9 * 32 * 8];     // [tap][m][j], ldm 8
    __shared__ __align__(16) float sB[6 * 130 * 12];   // [row][px+1][j], stride 12

    const int tid = threadIdx.x;
    const int wid = tid >> 5;
    const int r = wid >> 1, x0 = (wid & 1) << 6;   // warp: row r, px base x0
    const int band = blockIdx.x, img = blockIdx.y;

    const uint32_t sAu = smem_u32(sA), sBu = smem_u32(sB);

    wmma::fragment<wmma::accumulator, 16, 16, 8, float> acc[2][4];
#pragma unroll
    for (int wm = 0; wm < 2; wm++)
#pragma unroll
        for (int wn = 0; wn < 4; wn++) wmma::fill_fragment(acc[wm][wn], 0.f);

    for (int cc = 0; cc < 16; ++cc) {
        __syncthreads();                               // prior mma done
        // stage A: 9*32*8 = 2304 floats (576 x 16B), contiguous
        for (int e = tid; e < 576; e += 256)
            cpa16(sAu + e * 16, &g_w2t[cc * 2304 + e * 4], true);
        // stage B: 6 rows x 130 px x 8 ch (2 x 16B per px)
        for (int e = tid; e < 1560; e += 256) {
            int half = e & 1, p = e >> 1;              // p = row*130 + pxi
            int row = p / 130, pxi = p % 130;
            int yy = band * 4 - 1 + row;
            int xx = pxi - 1;
            bool ok = (unsigned)yy < (unsigned)Hc && (unsigned)xx < (unsigned)Wc;
            const float* src = ok ?
                &g_y1[((size_t)(img * Hc + yy) * Wc + xx) * 128 + cc * 8 +
                      half * 4] : g_y1;
            cpa16(sBu + (p * 12 + half * 4) * 4, src, ok);
        }
        cpa_commit();
        cpa_wait0();
        __syncthreads();

#pragma unroll
        for (int tap = 0; tap < 9; ++tap) {
            const int ky = tap / 3, kx = tap % 3;
            wmma::fragment<wmma::matrix_a, 16, 16, 8, wmma::precision::tf32,
                           wmma::row_major> af[2];
            wmma::fragment<wmma::matrix_b, 16, 16, 8, wmma::precision::tf32,
                           wmma::col_major> bf[4];
#pragma unroll
            for (int wm = 0; wm < 2; wm++)
                wmma::load_matrix_sync(af[wm],
                                       &sA[(tap * 32 + wm * 16) * 8], 8);
#pragma unroll
            for (int wn = 0; wn < 4; wn++)
                wmma::load_matrix_sync(
                    bf[wn],
                    &sB[((r + ky) * 130 + x0 + wn * 16 + kx) * 12], 12);
#pragma unroll
            for (int wm = 0; wm < 2; wm++)
#pragma unroll
                for (int wn = 0; wn < 4; wn++)
                    wmma::mma_sync(acc[wm][wn], af[wm], bf[wn], acc[wm][wn]);
        }
    }

    // store RAW (NCHW): row = band*4 + r
#pragma unroll
    for (int wm = 0; wm < 2; wm++)
#pragma unroll
        for (int wn = 0; wn < 4; wn++) {
            float* p = &g_y2[((size_t)(img * 32 + wm * 16) * Hc + band * 4 + r)
                             * Wc + x0 + wn * 16];
            wmma::store_matrix_sync(p, acc[wm][wn], Hc * Wc,
                                    wmma::mem_row_major);
        }
}

// ---------------------------------------------------------------------------
// Fused bilinear x2 upsample (half-pixel, edge clamp) + 3x3 conv 32->1.
// Reads conv2 RAW: applies relu(v + b2[ic]) during staging.
// ---------------------------------------------------------------------------
__global__ __launch_bounds__(256) void upconv3_k(
    const float* __restrict__ w3, const float* __restrict__ b2,
    const float* __restrict__ b3, float* __restrict__ out)
{
    __shared__ float sv[16][10][10];
    __shared__ float su[16][18][18];
    __shared__ float sw3[288];

    const int tid = threadIdx.x;
    const int tx = tid & 15, ty = tid >> 4;
    const int tileY = (blockIdx.x >> 4) << 4;
    const int tileX = (blockIdx.x & 15) << 4;
    const int n = blockIdx.y;
    const int m0 = tileY >> 1, q0 = tileX >> 1;

    for (int e = tid; e < 288; e += 256) sw3[e] = w3[e];

    float acc = 0.f;
    for (int c0 = 0; c0 < 32; c0 += 16) {
        __syncthreads();
        for (int e = tid; e < 16 * 10 * 10; e += 256) {
            int ic = e / 100, r = (e / 10) % 10, c = e % 10;
            int gy = min(max(m0 - 1 + r, 0), Hc - 1);
            int gx = min(max(q0 - 1 + c, 0), Wc - 1);
            float v = g_y2[((size_t)(n * 32 + c0 + ic) * Hc + gy) * Wc + gx];
            sv[ic][r][c] = fmaxf(v + b2[c0 + ic], 0.f);
        }
        __syncthreads();
        for (int e = tid; e < 16 * 18 * 18; e += 256) {
            int ic = e / 324, r = (e / 18) % 18, c = e % 18;
            int tyg = tileY - 1 + r, txg = tileX - 1 + c;
            float uv = 0.f;
            if ((unsigned)tyg < 256u && (unsigned)txg < 256u) {
                int i0y, i0x; float fy, fx;
                if (tyg & 1) { i0y = tyg >> 1;       fy = 0.25f; }
                else         { i0y = (tyg >> 1) - 1; fy = 0.75f; }
                if (txg & 1) { i0x = txg >> 1;       fx = 0.25f; }
                else         { i0x = (txg >> 1) - 1; fx = 0.75f; }
                int ly = i0y - (m0 - 1), lx = i0x - (q0 - 1);
                float v00 = sv[ic][ly][lx],     v01 = sv[ic][ly][lx + 1];
                float v10 = sv[ic][ly + 1][lx], v11 = sv[ic][ly + 1][lx + 1];
                float gy1 = 1.f - fy, gx1 = 1.f - fx;
                uv = gy1 * (gx1 * v00 + fx * v01) + fy * (gx1 * v10 + fx * v11);
            }
            su[ic][r][c] = uv;
        }
        __syncthreads();
#pragma unroll
        for (int ic = 0; ic < 16; ic++)
#pragma unroll
            for (int dy = 0; dy < 3; dy++)
#pragma unroll
                for (int dx = 0; dx < 3; dx++)
                    acc = fmaf(sw3[(c0 + ic) * 9 + dy * 3 + dx],
                               su[ic][ty + dy][tx + dx], acc);
    }
    acc += b3[0];
    out[((size_t)(n * 256) + tileY + ty) * 256 + tileX + tx] = acc;
}

// ---------------------------------------------------------------------------
extern "C" void kernel_launch(void* const* d_in, const int* in_sizes, int n_in,
                              void* d_out, int out_size)
{
    const float* x  = (const float*)d_in[0];
    const float* W1 = (const float*)d_in[3];
    const float* b1 = (const float*)d_in[4];
    const float* W2 = (const float*)d_in[5];
    const float* b2 = (const float*)d_in[6];
    const float* W3 = (const float*)d_in[7];
    const float* b3 = (const float*)d_in[8];
    float* out = (float*)d_out;

    xt_k<<<dim3(Hc, N_IMG), 256>>>(x);
    wt1_k<<<36 * 128 * 16 / 256, 256>>>(W1);
    wt2_k<<<16 * 9 * 32 * 8 / 256, 256>>>(W2);

    conv1_wmma_k<<<dim3(Hc, N_IMG), 256>>>(b1);
    conv2_wmma_k<<<dim3(Hc / 4, N_IMG), 256>>>();
    upconv3_k<<<dim3(256, N_IMG), 256>>>(W3, b2, b3, out);
}

// round 14
// speedup vs baseline: 7.3500x; 2.3467x over previous
#include <cuda_runtime.h>
#include <mma.h>
#include <cuda_fp16.h>
#include <cstdint>

using namespace nvcuda;

#define N_IMG 48
#define Hc 128
#define Wc 128

__device__ __half g_y1[48u * 128u * 128u * 128u];  // conv1 POST-act fp16, NHWC
__device__ float  g_y2[48u * 32u * 128u * 128u];   // conv2 RAW fp32, NCHW
__device__ __half g_xr[48u * 128u * 128u * 64u];   // x fp16, NHWC
__device__ __half g_w1t[36 * 128 * 16];            // W1 fp16 [c][m][16]
__device__ __half g_w2t[8 * 9 * 32 * 16];          // W2 fp16 [cc][tap][m][16]

__device__ __forceinline__ uint32_t smem_u32(const void* p) {
    uint32_t a;
    asm("{ .reg .u64 t; cvta.to.shared.u64 t, %1; cvt.u32.u64 %0, t; }"
        : "=r"(a) : "l"(p));
    return a;
}
__device__ __forceinline__ void cpa16(uint32_t dst, const void* src, bool ok) {
    int sz = ok ? 16 : 0;
    asm volatile("cp.async.cg.shared.global [%0], [%1], 16, %2;"
                 :: "r"(dst), "l"(src), "r"(sz) : "memory");
}
__device__ __forceinline__ void cpa_commit() {
    asm volatile("cp.async.commit_group;" ::: "memory");
}
__device__ __forceinline__ void cpa_wait0() {
    asm volatile("cp.async.wait_group 0;" ::: "memory");
}

// ---- prep: x NCHW fp32 -> g_xr NHWC fp16 ----------------------------------
__global__ __launch_bounds__(256) void xt_k(const float* __restrict__ x) {
    __shared__ float t[64][129];
    const int y = blockIdx.x, img = blockIdx.y;
    for (int e = threadIdx.x; e < 64 * 128; e += 256) {
        int ic = e >> 7, px = e & 127;
        t[ic][px] = x[((size_t)(img * 64 + ic) * Hc + y) * Wc + px];
    }
    __syncthreads();
    __half* dst = &g_xr[(size_t)(img * Hc + y) * Wc * 64];
    for (int e = threadIdx.x; e < 1024; e += 256) {
        int px = e >> 3, j = (e & 7) << 3;
        __half h[8];
#pragma unroll
        for (int q = 0; q < 8; q++) h[q] = __float2half_rn(t[j + q][px]);
        *(uint4*)&dst[px * 64 + j] = *(uint4*)h;
    }
}
// ---- prep: weight images fp16 ---------------------------------------------
__global__ __launch_bounds__(256) void wt1_k(const float* __restrict__ w) {
    int idx = blockIdx.x * 256 + threadIdx.x;          // < 36*128*16
    int kl = idx & 15, m = (idx >> 4) & 127, c = idx >> 11;
    int k = c * 16 + kl;
    int tap = k >> 6, ic = k & 63;
    g_w1t[idx] = __float2half_rn(w[(m * 64 + ic) * 9 + tap]);
}
__global__ __launch_bounds__(256) void wt2_k(const float* __restrict__ w) {
    int idx = blockIdx.x * 256 + threadIdx.x;          // < 8*9*32*16
    int j = idx & 15, m = (idx >> 4) & 31;
    int u = idx >> 9, tap = u % 9, cc = u / 9;
    int ic = cc * 16 + j;
    g_w2t[idx] = __float2half_rn(w[(m * 128 + ic) * 9 + tap]);
}

// ---------------------------------------------------------------------------
// conv1: fp16 wmma m16n16k16, cp.async(16B) double-buffered chunks of k16
// (tap, 16 ch). CTA: M=128 x N=128 px (one row). Warps 4x2, warp 32x64.
// Strides 24 halves (48B): LDSM-aligned, conflict-free. Epilogue: bias+relu,
// fp16 NHWC 16B stores.
// ---------------------------------------------------------------------------
__global__ __launch_bounds__(256, 2) void conv1_wmma_k(
    const float* __restrict__ b1)
{
    __shared__ __align__(16) __half sA[2][128 * 24];   // [m][kl], ldm 24
    __shared__ __align__(16) __half sB[2][128 * 24];   // [n][kl], ldm 24

    const int tid = threadIdx.x;
    const int lane = tid & 31, wid = tid >> 5;
    const int warpM = wid >> 1, warpN = wid & 1;
    const int band = blockIdx.x, img = blockIdx.y;

    const uint32_t sAu[2] = { smem_u32(sA[0]), smem_u32(sA[1]) };
    const uint32_t sBu[2] = { smem_u32(sB[0]), smem_u32(sB[1]) };

    auto issue = [&](int c, int buf) {
        const int tap = c >> 2, ic0 = (c & 3) << 4;
        const int ky = tap / 3, kx = tap % 3;
        const int yy = band + ky - 1;
        const bool yok = (unsigned)yy < (unsigned)Hc;
        {   // A: 128 m x 16 kl halves = 256 x 16B
            int m = tid >> 1, h = (tid & 1) << 3;
            cpa16(sAu[buf] + ((m * 24 + h) << 1),
                  &g_w1t[(c * 128 + m) * 16 + h], true);
        }
        {   // B: 128 px x 16 ch halves = 256 x 16B
            int n = tid >> 1, h = (tid & 1) << 3;
            int xx = n + kx - 1;
            bool ok = yok && (unsigned)xx < (unsigned)Wc;
            const __half* src = ok ?
                &g_xr[((size_t)(img * Hc + yy) * Wc + xx) * 64 + ic0 + h] : g_xr;
            cpa16(sBu[buf] + ((n * 24 + h) << 1), src, ok);
        }
        cpa_commit();
    };

    wmma::fragment<wmma::accumulator, 16, 16, 16, float> acc[2][4];
#pragma unroll
    for (int wm = 0; wm < 2; wm++)
#pragma unroll
        for (int wn = 0; wn < 4; wn++) wmma::fill_fragment(acc[wm][wn], 0.f);

    issue(0, 0);
    for (int c = 0; c < 36; ++c) {
        const int buf = c & 1;
        cpa_wait0();
        __syncthreads();
        if (c + 1 < 36) issue(c + 1, (c + 1) & 1);

        wmma::fragment<wmma::matrix_a, 16, 16, 16, __half,
                       wmma::row_major> af[2];
        wmma::fragment<wmma::matrix_b, 16, 16, 16, __half,
                       wmma::col_major> bf[4];
#pragma unroll
        for (int wm = 0; wm < 2; wm++)
            wmma::load_matrix_sync(af[wm],
                                   &sA[buf][(warpM * 32 + wm * 16) * 24], 24);
#pragma unroll
        for (int wn = 0; wn < 4; wn++)
            wmma::load_matrix_sync(bf[wn],
                                   &sB[buf][(warpN * 64 + wn * 16) * 24], 24);
#pragma unroll
        for (int wm = 0; wm < 2; wm++)
#pragma unroll
            for (int wn = 0; wn < 4; wn++)
                wmma::mma_sync(acc[wm][wn], af[wm], bf[wn], acc[wm][wn]);
    }

    // epilogue: bias+relu, NHWC fp16 16B stores (smem reused as fp32 scratch)
    __syncthreads();
    float* scr = reinterpret_cast<float*>(sA[0]) + wid * 272;
    const int px = lane >> 1, half = lane & 1;
#pragma unroll
    for (int wm = 0; wm < 2; wm++)
#pragma unroll
        for (int wn = 0; wn < 4; wn++) {
            wmma::store_matrix_sync(scr, acc[wm][wn], 16, wmma::mem_row_major);
            __syncwarp();
            int m0 = warpM * 32 + wm * 16 + half * 8;
            int n0 = warpN * 64 + wn * 16;
            __half hv[8];
#pragma unroll
            for (int j = 0; j < 8; j++)
                hv[j] = __float2half_rn(
                    fmaxf(scr[(half * 8 + j) * 16 + px] + b1[m0 + j], 0.f));
            __half* dp = &g_y1[((size_t)(img * Hc + band) * Wc + n0 + px) * 128
                               + m0];
            *(uint4*)dp = *(uint4*)hv;
            __syncwarp();
        }
}

// ---------------------------------------------------------------------------
// conv2: fp16 wmma m16n16k16, tap-reuse. CTA = 2 rows x 128 px x 32 oc.
// 8 ic-chunks of 16 ch. Per chunk: stage 4 input rows x 130 px x 16 ch
// (halo+pad) + A[tap][m][16]; 9 taps read B via smem offsets.
// Strides 24 halves. Stores RAW fp32 NCHW.
// ---------------------------------------------------------------------------
__global__ __launch_bounds__(256, 2) void conv2_wmma_k()
{
    __shared__ __align__(16) __half sA[9 * 32 * 24];    // [tap][m][kl], ldm 24
    __shared__ __align__(16) __half sB[4 * 130 * 24];   // [row][px+1][ch], 24

    const int tid = threadIdx.x;
    const int wid = tid >> 5;
    const int r = wid >> 2, x0 = (wid & 3) << 5;   // warp: row r, px base x0
    const int band = blockIdx.x, img = blockIdx.y;

    const uint32_t sAu = smem_u32(sA), sBu = smem_u32(sB);

    wmma::fragment<wmma::accumulator, 16, 16, 16, float> acc[2][2];
#pragma unroll
    for (int wm = 0; wm < 2; wm++)
#pragma unroll
        for (int wn = 0; wn < 2; wn++) wmma::fill_fragment(acc[wm][wn], 0.f);

    for (int cc = 0; cc < 8; ++cc) {
        __syncthreads();                               // prior mma done
        // stage A: 9 taps x 32 m x 16 kl halves = 576 x 16B
        for (int e = tid; e < 576; e += 256) {
            int q = e >> 1, h = (e & 1) << 3;          // q = tap*32 + m
            cpa16(sAu + ((q * 24 + h) << 1),
                  &g_w2t[((cc * 9) * 32 + q) * 16 + h], true);
        }
        // stage B: 4 rows x 130 px x 16 ch halves = 1040 x 16B
        for (int e = tid; e < 1040; e += 256) {
            int p = e >> 1, h = (e & 1) << 3;          // p = row*130 + pxi
            int row = p / 130, pxi = p % 130;
            int yy = band * 2 - 1 + row;
            int xx = pxi - 1;
            bool ok = (unsigned)yy < (unsigned)Hc && (unsigned)xx < (unsigned)Wc;
            const __half* src = ok ?
                &g_y1[((size_t)(img * Hc + yy) * Wc + xx) * 128 + cc * 16 + h]
                : g_y1;
            cpa16(sBu + ((p * 24 + h) << 1), src, ok);
        }
        cpa_commit();
        cpa_wait0();
        __syncthreads();

#pragma unroll
        for (int tap = 0; tap < 9; ++tap) {
            const int ky = tap / 3, kx = tap % 3;
            wmma::fragment<wmma::matrix_a, 16, 16, 16, __half,
                           wmma::row_major> af[2];
            wmma::fragment<wmma::matrix_b, 16, 16, 16, __half,
                           wmma::col_major> bf[2];
#pragma unroll
            for (int wm = 0; wm < 2; wm++)
                wmma::load_matrix_sync(af[wm],
                                       &sA[(tap * 32 + wm * 16) * 24], 24);
#pragma unroll
            for (int wn = 0; wn < 2; wn++)
                wmma::load_matrix_sync(
                    bf[wn],
                    &sB[((r + ky) * 130 + x0 + wn * 16 + kx) * 24], 24);
#pragma unroll
            for (int wm = 0; wm < 2; wm++)
#pragma unroll
                for (int wn = 0; wn < 2; wn++)
                    wmma::mma_sync(acc[wm][wn], af[wm], bf[wn], acc[wm][wn]);
        }
    }

    // store RAW fp32 (NCHW): row = band*2 + r
#pragma unroll
    for (int wm = 0; wm < 2; wm++)
#pragma unroll
        for (int wn = 0; wn < 2; wn++) {
            float* p = &g_y2[((size_t)(img * 32 + wm * 16) * Hc + band * 2 + r)
                             * Wc + x0 + wn * 16];
            wmma::store_matrix_sync(p, acc[wm][wn], Hc * Wc,
                                    wmma::mem_row_major);
        }
}

// ---------------------------------------------------------------------------
// Fused bilinear x2 upsample (half-pixel, edge clamp) + 3x3 conv 32->1.
// Reads conv2 RAW fp32: applies relu(v + b2[ic]) during staging.
// ---------------------------------------------------------------------------
__global__ __launch_bounds__(256) void upconv3_k(
    const float* __restrict__ w3, const float* __restrict__ b2,
    const float* __restrict__ b3, float* __restrict__ out)
{
    __shared__ float sv[16][10][10];
    __shared__ float su[16][18][18];
    __shared__ float sw3[288];

    const int tid = threadIdx.x;
    const int tx = tid & 15, ty = tid >> 4;
    const int tileY = (blockIdx.x >> 4) << 4;
    const int tileX = (blockIdx.x & 15) << 4;
    const int n = blockIdx.y;
    const int m0 = tileY >> 1, q0 = tileX >> 1;

    for (int e = tid; e < 288; e += 256) sw3[e] = w3[e];

    float acc = 0.f;
    for (int c0 = 0; c0 < 32; c0 += 16) {
        __syncthreads();
        for (int e = tid; e < 16 * 10 * 10; e += 256) {
            int ic = e / 100, r = (e / 10) % 10, c = e % 10;
            int gy = min(max(m0 - 1 + r, 0), Hc - 1);
            int gx = min(max(q0 - 1 + c, 0), Wc - 1);
            float v = g_y2[((size_t)(n * 32 + c0 + ic) * Hc + gy) * Wc + gx];
            sv[ic][r][c] = fmaxf(v + b2[c0 + ic], 0.f);
        }
        __syncthreads();
        for (int e = tid; e < 16 * 18 * 18; e += 256) {
            int ic = e / 324, r = (e / 18) % 18, c = e % 18;
            int tyg = tileY - 1 + r, txg = tileX - 1 + c;
            float uv = 0.f;
            if ((unsigned)tyg < 256u && (unsigned)txg < 256u) {
                int i0y, i0x; float fy, fx;
                if (tyg & 1) { i0y = tyg >> 1;       fy = 0.25f; }
                else         { i0y = (tyg >> 1) - 1; fy = 0.75f; }
                if (txg & 1) { i0x = txg >> 1;       fx = 0.25f; }
                else         { i0x = (txg >> 1) - 1; fx = 0.75f; }
                int ly = i0y - (m0 - 1), lx = i0x - (q0 - 1);
                float v00 = sv[ic][ly][lx],     v01 = sv[ic][ly][lx + 1];
                float v10 = sv[ic][ly + 1][lx], v11 = sv[ic][ly + 1][lx + 1];
                float gy1 = 1.f - fy, gx1 = 1.f - fx;
                uv = gy1 * (gx1 * v00 + fx * v01) + fy * (gx1 * v10 + fx * v11);
            }
            su[ic][r][c] = uv;
        }
        __syncthreads();
#pragma unroll
        for (int ic = 0; ic < 16; ic++)
#pragma unroll
            for (int dy = 0; dy < 3; dy++)
#pragma unroll
                for (int dx = 0; dx < 3; dx++)
                    acc = fmaf(sw3[(c0 + ic) * 9 + dy * 3 + dx],
                               su[ic][ty + dy][tx + dx], acc);
    }
    acc += b3[0];
    out[((size_t)(n * 256) + tileY + ty) * 256 + tileX + tx] = acc;
}

// ---------------------------------------------------------------------------
extern "C" void kernel_launch(void* const* d_in, const int* in_sizes, int n_in,
                              void* d_out, int out_size)
{
    const float* x  = (const float*)d_in[0];
    const float* W1 = (const float*)d_in[3];
    const float* b1 = (const float*)d_in[4];
    const float* W2 = (const float*)d_in[5];
    const float* b2 = (const float*)d_in[6];
    const float* W3 = (const float*)d_in[7];
    const float* b3 = (const float*)d_in[8];
    float* out = (float*)d_out;

    xt_k<<<dim3(Hc, N_IMG), 256>>>(x);
    wt1_k<<<36 * 128 * 16 / 256, 256>>>(W1);
    wt2_k<<<8 * 9 * 32 * 16 / 256, 256>>>(W2);

    conv1_wmma_k<<<dim3(Hc, N_IMG), 256>>>(b1);
    conv2_wmma_k<<<dim3(Hc / 2, N_IMG), 256>>>();
    upconv3_k<<<dim3(256, N_IMG), 256>>>(W3, b2, b3, out);
}

// round 15
// speedup vs baseline: 9.3936x; 1.2780x over previous
#include <cuda_runtime.h>
#include <mma.h>
#include <cuda_fp16.h>
#include <cstdint>

using namespace nvcuda;

#define N_IMG 48
#define Hc 128
#define Wc 128

__device__ __half g_y1[48u * 128u * 128u * 128u];  // conv1 POST-act fp16, NHWC
__device__ __half g_y2h[48u * 128u * 128u * 32u];  // conv2 POST-act fp16, NHWC
__device__ __half g_xr[48u * 128u * 128u * 64u];   // x fp16, NHWC
__device__ __half g_w1t[36 * 128 * 16];            // W1 fp16 [c][m][16]
__device__ __half g_w2t[8 * 9 * 32 * 16];          // W2 fp16 [cc][tap][m][16]
__device__ __half g_wu[9 * 16 * 32];               // Weff fp16 [tap][m(16)][ic]

__device__ __forceinline__ uint32_t smem_u32(const void* p) {
    uint32_t a;
    asm("{ .reg .u64 t; cvta.to.shared.u64 t, %1; cvt.u32.u64 %0, t; }"
        : "=r"(a) : "l"(p));
    return a;
}
__device__ __forceinline__ void cpa16(uint32_t dst, const void* src, bool ok) {
    int sz = ok ? 16 : 0;
    asm volatile("cp.async.cg.shared.global [%0], [%1], 16, %2;"
                 :: "r"(dst), "l"(src), "r"(sz) : "memory");
}
__device__ __forceinline__ void cpa_commit() {
    asm volatile("cp.async.commit_group;" ::: "memory");
}
__device__ __forceinline__ void cpa_wait0() {
    asm volatile("cp.async.wait_group 0;" ::: "memory");
}

// ---- prep: x NCHW fp32 -> g_xr NHWC fp16 ----------------------------------
__global__ __launch_bounds__(256) void xt_k(const float* __restrict__ x) {
    __shared__ float t[64][129];
    const int y = blockIdx.x, img = blockIdx.y;
    for (int e = threadIdx.x; e < 64 * 128; e += 256) {
        int ic = e >> 7, px = e & 127;
        t[ic][px] = x[((size_t)(img * 64 + ic) * Hc + y) * Wc + px];
    }
    __syncthreads();
    __half* dst = &g_xr[(size_t)(img * Hc + y) * Wc * 64];
    for (int e = threadIdx.x; e < 1024; e += 256) {
        int px = e >> 3, j = (e & 7) << 3;
        __half h[8];
#pragma unroll
        for (int q = 0; q < 8; q++) h[q] = __float2half_rn(t[j + q][px]);
        *(uint4*)&dst[px * 64 + j] = *(uint4*)h;
    }
}
// ---- prep: weight images fp16 ---------------------------------------------
__global__ __launch_bounds__(256) void wt1_k(const float* __restrict__ w) {
    int idx = blockIdx.x * 256 + threadIdx.x;          // < 36*128*16
    int kl = idx & 15, m = (idx >> 4) & 127, c = idx >> 11;
    int k = c * 16 + kl;
    int tap = k >> 6, ic = k & 63;
    g_w1t[idx] = __float2half_rn(w[(m * 64 + ic) * 9 + tap]);
}
__global__ __launch_bounds__(256) void wt2_k(const float* __restrict__ w) {
    int idx = blockIdx.x * 256 + threadIdx.x;          // < 8*9*32*16
    int j = idx & 15, m = (idx >> 4) & 31;
    int u = idx >> 9, tap = u % 9, cc = u / 9;
    int ic = cc * 16 + j;
    g_w2t[idx] = __float2half_rn(w[(m * 128 + ic) * 9 + tap]);
}
// ---- prep: effective upsample+conv3 weights per parity --------------------
// Weff[a][b][ic][r][s] = sum_{dy,dx} w3[ic][dy][dx] * Cy[a][dy][r] * Cx[b][dx][s]
__global__ __launch_bounds__(256) void wu_k(const float* __restrict__ w3) {
    int idx = blockIdx.x * 256 + threadIdx.x;          // < 9*16*32
    if (idx >= 9 * 16 * 32) return;
    int ic = idx & 31, m = (idx >> 5) & 15, tap = idx >> 9;
    float val = 0.f;
    if (m < 4) {
        const float CY[2][3][3] = {
            { {0.75f, 0.25f, 0.f}, {0.25f, 0.75f, 0.f}, {0.f, 0.75f, 0.25f} },
            { {0.25f, 0.75f, 0.f}, {0.f, 0.75f, 0.25f}, {0.f, 0.25f, 0.75f} } };
        int a = m >> 1, b = m & 1;
        int r = tap / 3, s = tap % 3;
        for (int dy = 0; dy < 3; dy++)
            for (int dx = 0; dx < 3; dx++)
                val += w3[ic * 9 + dy * 3 + dx] * CY[a][dy][r] * CY[b][dx][s];
    }
    g_wu[(tap * 16 + m) * 32 + ic] = __float2half_rn(val);
}

// ---------------------------------------------------------------------------
// conv1: unchanged (proven). fp16 wmma m16n16k16, cp.async double-buffer.
// ---------------------------------------------------------------------------
__global__ __launch_bounds__(256, 2) void conv1_wmma_k(
    const float* __restrict__ b1)
{
    __shared__ __align__(16) __half sA[2][128 * 24];   // [m][kl], ldm 24
    __shared__ __align__(16) __half sB[2][128 * 24];   // [n][kl], ldm 24

    const int tid = threadIdx.x;
    const int lane = tid & 31, wid = tid >> 5;
    const int warpM = wid >> 1, warpN = wid & 1;
    const int band = blockIdx.x, img = blockIdx.y;

    const uint32_t sAu[2] = { smem_u32(sA[0]), smem_u32(sA[1]) };
    const uint32_t sBu[2] = { smem_u32(sB[0]), smem_u32(sB[1]) };

    auto issue = [&](int c, int buf) {
        const int tap = c >> 2, ic0 = (c & 3) << 4;
        const int ky = tap / 3, kx = tap % 3;
        const int yy = band + ky - 1;
        const bool yok = (unsigned)yy < (unsigned)Hc;
        {
            int m = tid >> 1, h = (tid & 1) << 3;
            cpa16(sAu[buf] + ((m * 24 + h) << 1),
                  &g_w1t[(c * 128 + m) * 16 + h], true);
        }
        {
            int n = tid >> 1, h = (tid & 1) << 3;
            int xx = n + kx - 1;
            bool ok = yok && (unsigned)xx < (unsigned)Wc;
            const __half* src = ok ?
                &g_xr[((size_t)(img * Hc + yy) * Wc + xx) * 64 + ic0 + h] : g_xr;
            cpa16(sBu[buf] + ((n * 24 + h) << 1), src, ok);
        }
        cpa_commit();
    };

    wmma::fragment<wmma::accumulator, 16, 16, 16, float> acc[2][4];
#pragma unroll
    for (int wm = 0; wm < 2; wm++)
#pragma unroll
        for (int wn = 0; wn < 4; wn++) wmma::fill_fragment(acc[wm][wn], 0.f);

    issue(0, 0);
    for (int c = 0; c < 36; ++c) {
        const int buf = c & 1;
        cpa_wait0();
        __syncthreads();
        if (c + 1 < 36) issue(c + 1, (c + 1) & 1);

        wmma::fragment<wmma::matrix_a, 16, 16, 16, __half,
                       wmma::row_major> af[2];
        wmma::fragment<wmma::matrix_b, 16, 16, 16, __half,
                       wmma::col_major> bf[4];
#pragma unroll
        for (int wm = 0; wm < 2; wm++)
            wmma::load_matrix_sync(af[wm],
                                   &sA[buf][(warpM * 32 + wm * 16) * 24], 24);
#pragma unroll
        for (int wn = 0; wn < 4; wn++)
            wmma::load_matrix_sync(bf[wn],
                                   &sB[buf][(warpN * 64 + wn * 16) * 24], 24);
#pragma unroll
        for (int wm = 0; wm < 2; wm++)
#pragma unroll
            for (int wn = 0; wn < 4; wn++)
                wmma::mma_sync(acc[wm][wn], af[wm], bf[wn], acc[wm][wn]);
    }

    __syncthreads();
    float* scr = reinterpret_cast<float*>(sA[0]) + wid * 272;
    const int px = lane >> 1, half = lane & 1;
#pragma unroll
    for (int wm = 0; wm < 2; wm++)
#pragma unroll
        for (int wn = 0; wn < 4; wn++) {
            wmma::store_matrix_sync(scr, acc[wm][wn], 16, wmma::mem_row_major);
            __syncwarp();
            int m0 = warpM * 32 + wm * 16 + half * 8;
            int n0 = warpN * 64 + wn * 16;
            __half hv[8];
#pragma unroll
            for (int j = 0; j < 8; j++)
                hv[j] = __float2half_rn(
                    fmaxf(scr[(half * 8 + j) * 16 + px] + b1[m0 + j], 0.f));
            __half* dp = &g_y1[((size_t)(img * Hc + band) * Wc + n0 + px) * 128
                               + m0];
            *(uint4*)dp = *(uint4*)hv;
            __syncwarp();
        }
}

// ---------------------------------------------------------------------------
// conv2: mainloop unchanged; epilogue now bias+relu -> fp16 NHWC g_y2h.
// ---------------------------------------------------------------------------
__global__ __launch_bounds__(256, 2) void conv2_wmma_k(
    const float* __restrict__ b2)
{
    __shared__ __align__(16) __half sA[9 * 32 * 24];    // [tap][m][kl], ldm 24
    __shared__ __align__(16) __half sB[4 * 130 * 24];   // [row][px+1][ch], 24

    const int tid = threadIdx.x;
    const int lane = tid & 31, wid = tid >> 5;
    const int r = wid >> 2, x0 = (wid & 3) << 5;   // warp: row r, px base x0
    const int band = blockIdx.x, img = blockIdx.y;

    const uint32_t sAu = smem_u32(sA), sBu = smem_u32(sB);

    wmma::fragment<wmma::accumulator, 16, 16, 16, float> acc[2][2];
#pragma unroll
    for (int wm = 0; wm < 2; wm++)
#pragma unroll
        for (int wn = 0; wn < 2; wn++) wmma::fill_fragment(acc[wm][wn], 0.f);

    for (int cc = 0; cc < 8; ++cc) {
        __syncthreads();
        for (int e = tid; e < 576; e += 256) {
            int q = e >> 1, h = (e & 1) << 3;
            cpa16(sAu + ((q * 24 + h) << 1),
                  &g_w2t[((cc * 9) * 32 + q) * 16 + h], true);
        }
        for (int e = tid; e < 1040; e += 256) {
            int p = e >> 1, h = (e & 1) << 3;
            int row = p / 130, pxi = p % 130;
            int yy = band * 2 - 1 + row;
            int xx = pxi - 1;
            bool ok = (unsigned)yy < (unsigned)Hc && (unsigned)xx < (unsigned)Wc;
            const __half* src = ok ?
                &g_y1[((size_t)(img * Hc + yy) * Wc + xx) * 128 + cc * 16 + h]
                : g_y1;
            cpa16(sBu + ((p * 24 + h) << 1), src, ok);
        }
        cpa_commit();
        cpa_wait0();
        __syncthreads();

#pragma unroll
        for (int tap = 0; tap < 9; ++tap) {
            const int ky = tap / 3, kx = tap % 3;
            wmma::fragment<wmma::matrix_a, 16, 16, 16, __half,
                           wmma::row_major> af[2];
            wmma::fragment<wmma::matrix_b, 16, 16, 16, __half,
                           wmma::col_major> bf[2];
#pragma unroll
            for (int wm = 0; wm < 2; wm++)
                wmma::load_matrix_sync(af[wm],
                                       &sA[(tap * 32 + wm * 16) * 24], 24);
#pragma unroll
            for (int wn = 0; wn < 2; wn++)
                wmma::load_matrix_sync(
                    bf[wn],
                    &sB[((r + ky) * 130 + x0 + wn * 16 + kx) * 24], 24);
#pragma unroll
            for (int wm = 0; wm < 2; wm++)
#pragma unroll
                for (int wn = 0; wn < 2; wn++)
                    wmma::mma_sync(acc[wm][wn], af[wm], bf[wn], acc[wm][wn]);
        }
    }

    // epilogue: bias+relu -> fp16 NHWC (smem roundtrip, conv1 pattern)
    __syncthreads();
    float* scr = reinterpret_cast<float*>(sA) + wid * 272;
    const int px = lane >> 1, half = lane & 1;
    const int y = band * 2 + r;
#pragma unroll
    for (int wm = 0; wm < 2; wm++)
#pragma unroll
        for (int wn = 0; wn < 2; wn++) {
            wmma::store_matrix_sync(scr, acc[wm][wn], 16, wmma::mem_row_major);
            __syncwarp();
            int m0 = wm * 16 + half * 8;
            int x = x0 + wn * 16 + px;
            __half hv[8];
#pragma unroll
            for (int j = 0; j < 8; j++)
                hv[j] = __float2half_rn(
                    fmaxf(scr[(half * 8 + j) * 16 + px] + b2[m0 + j], 0.f));
            __half* dp = &g_y2h[((size_t)(img * Hc + y) * Wc + x) * 32 + m0];
            *(uint4*)dp = *(uint4*)hv;
            __syncwarp();
        }
}

// ---------------------------------------------------------------------------
// upconv as GEMM: out(2i+a, 2j+b) = b3 + sum_{ic,r,s} Weff[a][b][ic][r][s]
// * v[i+r-1][j+s-1] (v edge-clamped). M=16 (4 parities used), N=128 v-px,
// K=32ch x 9 taps (tap-reuse). CTA = 1 v row. Frame pixels fixed up after.
// ---------------------------------------------------------------------------
__global__ __launch_bounds__(256) void upconv_mma_k(
    const float* __restrict__ b3, float* __restrict__ out)
{
    __shared__ __align__(16) __half sA[9 * 16 * 40];    // [tap][m][ic], ldm 40
    __shared__ __align__(16) __half sB[3 * 130 * 40];   // [row][px+1][ic], 40

    const int tid = threadIdx.x;
    const int lane = tid & 31, wid = tid >> 5;
    const int i = blockIdx.x, img = blockIdx.y;   // v row
    const int j0 = wid << 4;                       // warp px base

    const uint32_t sAu = smem_u32(sA), sBu = smem_u32(sB);

    // stage A (Weff): 9 taps x 16 m x 32 ic halves = 576 x 16B
    for (int e = tid; e < 576; e += 256) {
        int q = e >> 2, h = (e & 3) << 3;          // q = tap*16 + m
        cpa16(sAu + ((q * 40 + h) << 1), &g_wu[q * 32 + h], true);
    }
    // stage B (v, clamped): 3 rows x 130 px x 32 ch halves = 1560 x 16B
    for (int e = tid; e < 1560; e += 256) {
        int p = e >> 2, h = (e & 2 ? 16 : 0) + ((e & 1) << 3);
        int row = p / 130, pxi = p % 130;
        int vy = min(max(i - 1 + row, 0), Hc - 1);
        int vx = min(max(pxi - 1, 0), Wc - 1);
        cpa16(sBu + ((p * 40 + h) << 1),
              &g_y2h[((size_t)(img * Hc + vy) * Wc + vx) * 32 + h], true);
    }
    cpa_commit();
    cpa_wait0();
    __syncthreads();

    wmma::fragment<wmma::accumulator, 16, 16, 16, float> acc;
    wmma::fill_fragment(acc, 0.f);

#pragma unroll
    for (int tap = 0; tap < 9; ++tap) {
        const int r = tap / 3, s = tap % 3;
#pragma unroll
        for (int ks = 0; ks < 2; ++ks) {
            wmma::fragment<wmma::matrix_a, 16, 16, 16, __half,
                           wmma::row_major> af;
            wmma::fragment<wmma::matrix_b, 16, 16, 16, __half,
                           wmma::col_major> bf;
            wmma::load_matrix_sync(af, &sA[(tap * 16) * 40 + ks * 16], 40);
            wmma::load_matrix_sync(bf, &sB[(r * 130 + j0 + s) * 40 + ks * 16],
                                   40);
            wmma::mma_sync(acc, af, bf, acc);
        }
    }

    // epilogue: scatter 4 parities to 2x2 output blocks
    __syncthreads();
    float* scr = reinterpret_cast<float*>(sB) + wid * 272;
    wmma::store_matrix_sync(scr, acc, 16, wmma::mem_row_major);
    __syncwarp();
    const float bv = b3[0];
    float* op = &out[(size_t)img * 256 * 256];
#pragma unroll
    for (int e = lane; e < 64; e += 32) {
        int m = e >> 4, j = e & 15;
        int a = m >> 1, b = m & 1;
        op[(2 * i + a) * 256 + 2 * (j0 + j) + b] = scr[m * 16 + j] + bv;
    }
}

// ---------------------------------------------------------------------------
// Border fixup: recompute the 1-px output frame exactly (conv3 zero-pad).
// ---------------------------------------------------------------------------
__global__ __launch_bounds__(256) void border_k(
    const float* __restrict__ w3, const float* __restrict__ b3,
    float* __restrict__ out)
{
    const int img = blockIdx.x;
    const __half* v = &g_y2h[(size_t)img * Hc * Wc * 32];
    for (int pid = threadIdx.x; pid < 1020; pid += 256) {
        int ty, tx;
        if (pid < 256)      { ty = 0;            tx = pid; }
        else if (pid < 512) { ty = 255;          tx = pid - 256; }
        else if (pid < 766) { ty = pid - 512 + 1; tx = 0; }
        else                { ty = pid - 766 + 1; tx = 255; }

        float acc = 0.f;
        for (int dy = 0; dy < 3; dy++) {
            int t = ty + dy - 1;
            if ((unsigned)t >= 256u) continue;
            int p0, p1; float wy0, wy1;
            if (t & 1) { p0 = t >> 1; p1 = p0 + 1; wy0 = 0.75f; wy1 = 0.25f; }
            else       { p0 = (t >> 1) - 1; p1 = t >> 1; wy0 = 0.25f; wy1 = 0.75f; }
            p0 = min(max(p0, 0), Hc - 1); p1 = min(max(p1, 0), Hc - 1);
            for (int dx = 0; dx < 3; dx++) {
                int s = tx + dx - 1;
                if ((unsigned)s >= 256u) continue;
                int q0, q1; float wx0, wx1;
                if (s & 1) { q0 = s >> 1; q1 = q0 + 1; wx0 = 0.75f; wx1 = 0.25f; }
                else       { q0 = (s >> 1) - 1; q1 = s >> 1; wx0 = 0.25f; wx1 = 0.75f; }
                q0 = min(max(q0, 0), Wc - 1); q1 = min(max(q1, 0), Wc - 1);
                const __half* v00 = &v[(p0 * Wc + q0) * 32];
                const __half* v01 = &v[(p0 * Wc + q1) * 32];
                const __half* v10 = &v[(p1 * Wc + q0) * 32];
                const __half* v11 = &v[(p1 * Wc + q1) * 32];
                for (int ic = 0; ic < 32; ic++) {
                    float u = wy0 * (wx0 * __half2float(v00[ic]) +
                                     wx1 * __half2float(v01[ic])) +
                              wy1 * (wx0 * __half2float(v10[ic]) +
                                     wx1 * __half2float(v11[ic]));
                    acc += w3[ic * 9 + dy * 3 + dx] * u;
                }
            }
        }
        out[((size_t)img * 256 + ty) * 256 + tx] = acc + b3[0];
    }
}

// ---------------------------------------------------------------------------
extern "C" void kernel_launch(void* const* d_in, const int* in_sizes, int n_in,
                              void* d_out, int out_size)
{
    const float* x  = (const float*)d_in[0];
    const float* W1 = (const float*)d_in[3];
    const float* b1 = (const float*)d_in[4];
    const float* W2 = (const float*)d_in[5];
    const float* b2 = (const float*)d_in[6];
    const float* W3 = (const float*)d_in[7];
    const float* b3 = (const float*)d_in[8];
    float* out = (float*)d_out;

    xt_k<<<dim3(Hc, N_IMG), 256>>>(x);
    wt1_k<<<36 * 128 * 16 / 256, 256>>>(W1);
    wt2_k<<<8 * 9 * 32 * 16 / 256, 256>>>(W2);
    wu_k<<<(9 * 16 * 32 + 255) / 256, 256>>>(W3);

    conv1_wmma_k<<<dim3(Hc, N_IMG), 256>>>(b1);
    conv2_wmma_k<<<dim3(Hc / 2, N_IMG), 256>>>(b2);
    upconv_mma_k<<<dim3(Hc, N_IMG), 256>>>(b3, out);
    border_k<<<N_IMG, 256>>>(W3, b3, out);
}